// round 7
// baseline (speedup 1.0000x reference)
#include <cuda_runtime.h>

#define NN 100000
#define NE 1600000
#define F 128
#define NBLK 98   // ceil(NN/1024)
#define KC 16     // GEMM k-chunk

// -------- scratch (static device globals; no allocations allowed) ----------
__device__ float g_dinv[NN];                 // deg -> deg^-1/2
__device__ int   g_deg[NN];                  // integer in-degree (dst)
__device__ int   g_part[NBLK];               // scan partials
__device__ int   g_rowptr[NN + 1];           // CSR row pointers (by dst)
__device__ int   g_cursor[NN];               // fill cursors
__device__ __align__(16) int2 g_csr[NE];     // CSR: (src, w-as-int) per edge
__device__ float g_h[(size_t)NN * F];        // h = act(prev) @ W
__device__ float g_buf[(size_t)NN * F];      // layer output (agg + self + b)
__device__ float g_hf[NN];                   // final-layer per-node scalar

// ------------------------- packed f32x2 helpers -----------------------------
__device__ __forceinline__ void fma2(unsigned long long& d,
                                     unsigned long long a,
                                     unsigned long long b) {
    asm("fma.rn.f32x2 %0, %1, %2, %0;" : "+l"(d) : "l"(a), "l"(b));
}
__device__ __forceinline__ float2 unpack2(unsigned long long v) {
    float2 f;
    asm("mov.b64 {%0, %1}, %2;" : "=f"(f.x), "=f"(f.y) : "l"(v));
    return f;
}

// ---------------------------- normalization --------------------------------
__global__ void k_deg_init() {
    int i = blockIdx.x * blockDim.x + threadIdx.x;
    if (i < NN) { g_dinv[i] = 1.0f; g_deg[i] = 0; }   // self-loop weight 1
}

__global__ void k_deg_acc(const int* __restrict__ ei,
                          const float* __restrict__ ew) {
    int e = blockIdx.x * blockDim.x + threadIdx.x;
    if (e < NE) {
        int d = ei[NE + e];
        atomicAdd(&g_dinv[d], ew[e]);
        atomicAdd(&g_deg[d], 1);
    }
}

// --------------------- 3-phase parallel exclusive scan ----------------------
__global__ __launch_bounds__(1024) void k_scan1() {
    __shared__ int s[1024];
    int t = threadIdx.x, i = blockIdx.x * 1024 + t;
    if (i < NN) g_dinv[i] = rsqrtf(g_dinv[i]);   // deg >= 1 always
    s[t] = (i < NN) ? g_deg[i] : 0;
    __syncthreads();
    for (int off = 512; off; off >>= 1) {
        if (t < off) s[t] += s[t + off];
        __syncthreads();
    }
    if (t == 0) g_part[blockIdx.x] = s[0];
}

__global__ __launch_bounds__(128) void k_scan2() {
    __shared__ int s[128];
    int t = threadIdx.x;
    int v = (t < NBLK) ? g_part[t] : 0;
    s[t] = v;
    __syncthreads();
    for (int off = 1; off < 128; off <<= 1) {
        int u = (t >= off) ? s[t - off] : 0;
        __syncthreads();
        s[t] += u;
        __syncthreads();
    }
    if (t < NBLK) g_part[t] = s[t] - v;          // exclusive prefix of partials
    if (t == 127) g_rowptr[NN] = s[127];         // total edge count
}

__global__ __launch_bounds__(1024) void k_scan3() {
    __shared__ int s[1024];
    int t = threadIdx.x, i = blockIdx.x * 1024 + t;
    int v = (i < NN) ? g_deg[i] : 0;
    s[t] = v;
    __syncthreads();
    for (int off = 1; off < 1024; off <<= 1) {
        int u = (t >= off) ? s[t - off] : 0;
        __syncthreads();
        s[t] += u;
        __syncthreads();
    }
    if (i < NN) {
        int ex = s[t] - v + g_part[blockIdx.x];
        g_rowptr[i] = ex;
        g_cursor[i] = ex;
    }
}

// place each edge into CSR, computing its normalization on the fly
__global__ void k_fill(const int* __restrict__ ei,
                       const float* __restrict__ ew) {
    int e = blockIdx.x * blockDim.x + threadIdx.x;
    if (e >= NE) return;
    int s = ei[e], d = ei[NE + e];
    int pos = atomicAdd(&g_cursor[d], 1);
    float w = g_dinv[s] * ew[e] * g_dinv[d];
    g_csr[pos] = make_int2(s, __float_as_int(w));
}

// ------------------------------- GEMM ---------------------------------------
// 128x128 block tile, 256 threads, 8x8 micro-tile via packed fma.rn.f32x2.
// acc[r][cp] = packed pair over columns (2cp, 2cp+1); A replicated {a,a} in smem.
__global__ __launch_bounds__(256) void k_gemm(const float* __restrict__ Aext,
                                              const float* __restrict__ W,
                                              int use_gbuf, int relu_in) {
    const float* __restrict__ A = use_gbuf ? (const float*)g_buf : Aext;
    __shared__ __align__(16) float2 Asp[KC][130];   // [k][row], {v,v}, padded
    __shared__ __align__(16) float  Ws[KC][128];    // [k][col]
    int tid = threadIdx.x;
    int tx = tid & 15;                // 16 col-groups of 8 (4 pairs)
    int ty = tid >> 4;                // 16 row-groups of 8
    int row0 = blockIdx.x * 128;
    unsigned long long acc[8][4] = {};   // bit-zero == {0.f, 0.f}

    for (int kc = 0; kc < F; kc += KC) {
        // A tile: 128 rows x 16 k = 512 float4 (2/thread), replicated into Asp
        #pragma unroll
        for (int i = 0; i < 2; i++) {
            int idx = tid + i * 256;
            int r = idx >> 2, k4 = idx & 3;
            int row = row0 + r;
            float4 v = make_float4(0.f, 0.f, 0.f, 0.f);
            if (row < NN) v = *(const float4*)&A[(size_t)row * F + kc + k4 * 4];
            if (relu_in) {
                v.x = fmaxf(v.x, 0.f); v.y = fmaxf(v.y, 0.f);
                v.z = fmaxf(v.z, 0.f); v.w = fmaxf(v.w, 0.f);
            }
            Asp[k4 * 4 + 0][r] = make_float2(v.x, v.x);
            Asp[k4 * 4 + 1][r] = make_float2(v.y, v.y);
            Asp[k4 * 4 + 2][r] = make_float2(v.z, v.z);
            Asp[k4 * 4 + 3][r] = make_float2(v.w, v.w);
        }
        // W tile: 16 x 128 = 512 float4 (2/thread)
        #pragma unroll
        for (int i = 0; i < 2; i++) {
            int idx = tid + i * 256;
            int k = idx >> 5, c4 = idx & 31;
            *(float4*)&Ws[k][c4 * 4] = *(const float4*)&W[(kc + k) * F + c4 * 4];
        }
        __syncthreads();
        #pragma unroll
        for (int k = 0; k < KC; k++) {
            // 4 natural column pairs from two LDS.128
            ulonglong2 wA = *(const ulonglong2*)&Ws[k][tx * 8];
            ulonglong2 wB = *(const ulonglong2*)&Ws[k][tx * 8 + 4];
            #pragma unroll
            for (int r = 0; r < 8; r++) {
                unsigned long long av =
                    *(const unsigned long long*)&Asp[k][ty * 8 + r];
                fma2(acc[r][0], av, wA.x);
                fma2(acc[r][1], av, wA.y);
                fma2(acc[r][2], av, wB.x);
                fma2(acc[r][3], av, wB.y);
            }
        }
        __syncthreads();
    }
    #pragma unroll
    for (int r = 0; r < 8; r++) {
        int row = row0 + ty * 8 + r;
        if (row < NN) {
            float2 p0 = unpack2(acc[r][0]), p1 = unpack2(acc[r][1]);
            float2 p2 = unpack2(acc[r][2]), p3 = unpack2(acc[r][3]);
            *(float4*)&g_h[(size_t)row * F + tx * 8] =
                make_float4(p0.x, p0.y, p1.x, p1.y);
            *(float4*)&g_h[(size_t)row * F + tx * 8 + 4] =
                make_float4(p2.x, p2.y, p3.x, p3.y);
        }
    }
}

// ----------------------- aggregation: CSR gather ----------------------------
// Warp per node, float4 per lane. If do_dot: emit g_hf[n]=relu(row).Wf instead.
__global__ __launch_bounds__(256) void k_gather(const float* __restrict__ b,
                                                int do_dot,
                                                const float* __restrict__ Wf) {
    int node = blockIdx.x * 8 + (threadIdx.x >> 5);
    int lane = threadIdx.x & 31;
    if (node >= NN) return;
    const float4* __restrict__ h4 = (const float4*)g_h;

    float dv = g_dinv[node];
    float4 hv = h4[(size_t)node * 32 + lane];
    float s2 = dv * dv;
    float4 acc;
    float4 bv = *(const float4*)&b[lane * 4];
    acc.x = s2 * hv.x + bv.x; acc.y = s2 * hv.y + bv.y;
    acc.z = s2 * hv.z + bv.z; acc.w = s2 * hv.w + bv.w;

    int beg = g_rowptr[node], end = g_rowptr[node + 1];
    int e = beg;
    if ((e & 1) && e < end) {                    // peel to 16B alignment
        int2 p = g_csr[e];
        float w = __int_as_float(p.y);
        float4 v = h4[(size_t)p.x * 32 + lane];
        acc.x += w * v.x; acc.y += w * v.y;
        acc.z += w * v.z; acc.w += w * v.w;
        e++;
    }
    for (; e + 2 <= end; e += 2) {
        int4 p = *(const int4*)&g_csr[e];        // two (src,w) pairs, aligned
        float w0 = __int_as_float(p.y);
        float w1 = __int_as_float(p.w);
        float4 v0 = h4[(size_t)p.x * 32 + lane];
        float4 v1 = h4[(size_t)p.z * 32 + lane];
        acc.x += w0 * v0.x; acc.y += w0 * v0.y;
        acc.z += w0 * v0.z; acc.w += w0 * v0.w;
        acc.x += w1 * v1.x; acc.y += w1 * v1.y;
        acc.z += w1 * v1.z; acc.w += w1 * v1.w;
    }
    if (e < end) {
        int2 p = g_csr[e];
        float w = __int_as_float(p.y);
        float4 v = h4[(size_t)p.x * 32 + lane];
        acc.x += w * v.x; acc.y += w * v.y;
        acc.z += w * v.z; acc.w += w * v.w;
    }

    if (!do_dot) {
        ((float4*)g_buf)[(size_t)node * 32 + lane] = acc;
    } else {
        acc.x = fmaxf(acc.x, 0.f); acc.y = fmaxf(acc.y, 0.f);
        acc.z = fmaxf(acc.z, 0.f); acc.w = fmaxf(acc.w, 0.f);
        float4 wf = *(const float4*)&Wf[lane * 4];
        float sum = acc.x * wf.x + acc.y * wf.y + acc.z * wf.z + acc.w * wf.w;
        #pragma unroll
        for (int o = 16; o; o >>= 1) sum += __shfl_xor_sync(0xffffffffu, sum, o);
        if (lane == 0) g_hf[node] = sum;
    }
}

// ------------------------------ final layer --------------------------------
__global__ void k_fin(const float* __restrict__ bf, float* __restrict__ out) {
    int i = blockIdx.x * blockDim.x + threadIdx.x;
    if (i >= NN) return;
    float dv = g_dinv[i];
    float acc = dv * dv * g_hf[i] + bf[0];
    int beg = g_rowptr[i], end = g_rowptr[i + 1];
    for (int e = beg; e < end; e++) {
        int2 p = g_csr[e];
        acc += __int_as_float(p.y) * g_hf[p.x];
    }
    out[i] = acc;
}

// ------------------------------- launch ------------------------------------
extern "C" void kernel_launch(void* const* d_in, const int* in_sizes, int n_in,
                              void* d_out, int out_size) {
    const float* x   = (const float*)d_in[0];
    const int*   ei  = (const int*)d_in[1];
    const float* ew  = (const float*)d_in[2];
    const float* Win = (const float*)d_in[3];
    const float* bin = (const float*)d_in[4];
    const float* Wmd = (const float*)d_in[5];
    const float* bmd = (const float*)d_in[6];
    const float* Wfn = (const float*)d_in[7];
    const float* bfn = (const float*)d_in[8];
    float* out = (float*)d_out;

    const int TB = 256;
    const int gN = (NN + TB - 1) / TB;           // 391
    const int gE = (NE + TB - 1) / TB;           // 6250
    const int gG = (NN + 127) / 128;             // 782
    const int gA = (NN + 7) / 8;                 // 12500 (warp/node)

    k_deg_init<<<gN, TB>>>();                    // 0
    k_deg_acc<<<gE, TB>>>(ei, ew);               // 1
    k_scan1<<<NBLK, 1024>>>();                   // 2 (also rsqrt)
    k_scan2<<<1, 128>>>();                       // 3
    k_scan3<<<NBLK, 1024>>>();                   // 4
    k_gemm<<<gG, TB>>>(x, Win, 0, 0);            // 5
    k_fill<<<gE, TB>>>(ei, ew);                  // 6

    // layer 1 aggregate
    k_gather<<<gA, TB>>>(bin, 0, nullptr);

    // layer 2
    k_gemm<<<gG, TB>>>(nullptr, Wmd, 1, 1);
    k_gather<<<gA, TB>>>(bmd, 0, nullptr);

    // layer 3 (+ fused final dot)
    k_gemm<<<gG, TB>>>(nullptr, Wmd, 1, 1);
    k_gather<<<gA, TB>>>(bmd, 1, Wfn);

    // final aggregation (scalar)
    k_fin<<<gN, TB>>>(bfn, out);
}

// round 9
// speedup vs baseline: 1.3295x; 1.3295x over previous
#include <cuda_runtime.h>
#include <cuda_bf16.h>
#include <mma.h>
#include <cstdint>

using namespace nvcuda;

#define NN 100000
#define NNP 100096   // padded to multiple of 128 for unguarded wmma stores
#define NE 1600000
#define F 128
#define NBLK 98      // ceil(NN/1024)
#define AP 40        // A smem pitch (bf16)
#define WP 136       // W smem pitch (bf16)

// -------- scratch (static device globals; no allocations allowed) ----------
__device__ float g_dinv[NN];
__device__ int   g_deg[NN];
__device__ int   g_part[NBLK];
__device__ int   g_rowptr[NN + 1];
__device__ int   g_cursor[NN];
__device__ __align__(16) int2 g_csr[NE];
__device__ float g_h[(size_t)NNP * F];
__device__ float g_buf[(size_t)NNP * F];
__device__ float g_hf[NN];
__device__ __align__(16) __nv_bfloat16 g_Whi[2][F * F];  // [0]=W_in, [1]=W_mid
__device__ __align__(16) __nv_bfloat16 g_Wlo[2][F * F];

// ---------------------------- normalization --------------------------------
__global__ void k_deg_init() {
    int i = blockIdx.x * blockDim.x + threadIdx.x;
    if (i < NN) { g_dinv[i] = 1.0f; g_deg[i] = 0; }
}

__global__ void k_deg_acc(const int* __restrict__ ei,
                          const float* __restrict__ ew) {
    int e = blockIdx.x * blockDim.x + threadIdx.x;
    if (e < NE) {
        int d = ei[NE + e];
        atomicAdd(&g_dinv[d], ew[e]);
        atomicAdd(&g_deg[d], 1);
    }
}

// W split: row-major [k][n] -> hi/lo bf16
__global__ void k_wsplit(const float* __restrict__ W, int which) {
    int i = blockIdx.x * blockDim.x + threadIdx.x;   // 0..16383
    float w = W[i];
    __nv_bfloat16 h = __float2bfloat16(w);
    g_Whi[which][i] = h;
    g_Wlo[which][i] = __float2bfloat16(w - __bfloat162float(h));
}

// --------------------- 3-phase parallel exclusive scan ----------------------
__global__ __launch_bounds__(1024) void k_scan1() {
    __shared__ int s[1024];
    int t = threadIdx.x, i = blockIdx.x * 1024 + t;
    if (i < NN) g_dinv[i] = rsqrtf(g_dinv[i]);
    s[t] = (i < NN) ? g_deg[i] : 0;
    __syncthreads();
    for (int off = 512; off; off >>= 1) {
        if (t < off) s[t] += s[t + off];
        __syncthreads();
    }
    if (t == 0) g_part[blockIdx.x] = s[0];
}

__global__ __launch_bounds__(128) void k_scan2() {
    __shared__ int s[128];
    int t = threadIdx.x;
    int v = (t < NBLK) ? g_part[t] : 0;
    s[t] = v;
    __syncthreads();
    for (int off = 1; off < 128; off <<= 1) {
        int u = (t >= off) ? s[t - off] : 0;
        __syncthreads();
        s[t] += u;
        __syncthreads();
    }
    if (t < NBLK) g_part[t] = s[t] - v;
    if (t == 127) g_rowptr[NN] = s[127];
}

__global__ __launch_bounds__(1024) void k_scan3() {
    __shared__ int s[1024];
    int t = threadIdx.x, i = blockIdx.x * 1024 + t;
    int v = (i < NN) ? g_deg[i] : 0;
    s[t] = v;
    __syncthreads();
    for (int off = 1; off < 1024; off <<= 1) {
        int u = (t >= off) ? s[t - off] : 0;
        __syncthreads();
        s[t] += u;
        __syncthreads();
    }
    if (i < NN) {
        int ex = s[t] - v + g_part[blockIdx.x];
        g_rowptr[i] = ex;
        g_cursor[i] = ex;
    }
}

__global__ void k_fill(const int* __restrict__ ei,
                       const float* __restrict__ ew) {
    int e = blockIdx.x * blockDim.x + threadIdx.x;
    if (e >= NE) return;
    int s = ei[e], d = ei[NE + e];
    int pos = atomicAdd(&g_cursor[d], 1);
    float w = g_dinv[s] * ew[e] * g_dinv[d];
    g_csr[pos] = make_int2(s, __float_as_int(w));
}

// --------------- tensor-core GEMM: wmma bf16 two-term split -----------------
// h[tile, 128] = act(A) @ W ~= Ahi*Whi + Ahi*Wlo + Alo*Whi  (fp32 accum)
__global__ __launch_bounds__(256) void k_gemm_tc(const float* __restrict__ Aext,
                                                 int widx, int use_gbuf,
                                                 int relu_in) {
    const float* __restrict__ A = use_gbuf ? (const float*)g_buf : Aext;
    __shared__ __nv_bfloat16 Ah[128 * AP];
    __shared__ __nv_bfloat16 Al[128 * AP];
    __shared__ __nv_bfloat16 Wh[32 * WP];
    __shared__ __nv_bfloat16 Wl[32 * WP];
    int tid = threadIdx.x;
    int wid = tid >> 5;
    int row0 = blockIdx.x * 128;
    const __nv_bfloat16* __restrict__ Whig = g_Whi[widx];
    const __nv_bfloat16* __restrict__ Wlog = g_Wlo[widx];

    wmma::fragment<wmma::accumulator, 16, 16, 16, float> acc[8];
    #pragma unroll
    for (int c = 0; c < 8; c++) wmma::fill_fragment(acc[c], 0.0f);

    for (int kc = 0; kc < F; kc += 32) {
        // A chunk 128x32 fp32 -> split bf16 smem (1024 float4, 4/thread)
        #pragma unroll
        for (int i = 0; i < 4; i++) {
            int idx = tid + i * 256;
            int r = idx >> 3, c4 = idx & 7;
            int row = row0 + r;
            float4 v = make_float4(0.f, 0.f, 0.f, 0.f);
            if (row < NN) v = *(const float4*)&A[(size_t)row * F + kc + c4 * 4];
            if (relu_in) {
                v.x = fmaxf(v.x, 0.f); v.y = fmaxf(v.y, 0.f);
                v.z = fmaxf(v.z, 0.f); v.w = fmaxf(v.w, 0.f);
            }
            __nv_bfloat162 h01 = __floats2bfloat162_rn(v.x, v.y);
            __nv_bfloat162 h23 = __floats2bfloat162_rn(v.z, v.w);
            *(__nv_bfloat162*)&Ah[r * AP + c4 * 4]     = h01;
            *(__nv_bfloat162*)&Ah[r * AP + c4 * 4 + 2] = h23;
            __nv_bfloat162 l01 = __floats2bfloat162_rn(v.x - __low2float(h01),
                                                       v.y - __high2float(h01));
            __nv_bfloat162 l23 = __floats2bfloat162_rn(v.z - __low2float(h23),
                                                       v.w - __high2float(h23));
            *(__nv_bfloat162*)&Al[r * AP + c4 * 4]     = l01;
            *(__nv_bfloat162*)&Al[r * AP + c4 * 4 + 2] = l23;
        }
        // W chunk 32x128 bf16 copy (512 int4 per image, 2/thread)
        #pragma unroll
        for (int i = 0; i < 2; i++) {
            int idx = tid + i * 256;
            int k = idx >> 4, c16 = idx & 15;
            *(int4*)&Wh[k * WP + c16 * 8] =
                *(const int4*)&Whig[(kc + k) * F + c16 * 8];
            *(int4*)&Wl[k * WP + c16 * 8] =
                *(const int4*)&Wlog[(kc + k) * F + c16 * 8];
        }
        __syncthreads();

        #pragma unroll
        for (int ks = 0; ks < 32; ks += 16) {
            wmma::fragment<wmma::matrix_a, 16, 16, 16, __nv_bfloat16,
                           wmma::row_major> ah, al;
            wmma::load_matrix_sync(ah, &Ah[(wid * 16) * AP + ks], AP);
            wmma::load_matrix_sync(al, &Al[(wid * 16) * AP + ks], AP);
            #pragma unroll
            for (int c = 0; c < 8; c++) {
                wmma::fragment<wmma::matrix_b, 16, 16, 16, __nv_bfloat16,
                               wmma::row_major> bh, bl;
                wmma::load_matrix_sync(bh, &Wh[ks * WP + c * 16], WP);
                wmma::load_matrix_sync(bl, &Wl[ks * WP + c * 16], WP);
                wmma::mma_sync(acc[c], ah, bh, acc[c]);
                wmma::mma_sync(acc[c], ah, bl, acc[c]);
                wmma::mma_sync(acc[c], al, bh, acc[c]);
            }
        }
        __syncthreads();
    }
    // store 16x128 per warp; g_h is row-padded so no guard needed
    float* outp = &g_h[(size_t)(row0 + wid * 16) * F];
    #pragma unroll
    for (int c = 0; c < 8; c++)
        wmma::store_matrix_sync(outp + c * 16, acc[c], F, wmma::mem_row_major);
}

// ----------------------- aggregation: CSR gather ----------------------------
__global__ __launch_bounds__(256) void k_gather(const float* __restrict__ b,
                                                int do_dot,
                                                const float* __restrict__ Wf) {
    int node = blockIdx.x * 8 + (threadIdx.x >> 5);
    int lane = threadIdx.x & 31;
    if (node >= NN) return;
    const float4* __restrict__ h4 = (const float4*)g_h;

    float dv = g_dinv[node];
    float4 hv = h4[(size_t)node * 32 + lane];
    float s2 = dv * dv;
    float4 acc;
    float4 bv = *(const float4*)&b[lane * 4];
    acc.x = s2 * hv.x + bv.x; acc.y = s2 * hv.y + bv.y;
    acc.z = s2 * hv.z + bv.z; acc.w = s2 * hv.w + bv.w;

    int beg = g_rowptr[node], end = g_rowptr[node + 1];
    int e = beg;
    if ((e & 1) && e < end) {                    // peel to 16B alignment
        int2 p = g_csr[e];
        float w = __int_as_float(p.y);
        float4 v = h4[(size_t)p.x * 32 + lane];
        acc.x += w * v.x; acc.y += w * v.y;
        acc.z += w * v.z; acc.w += w * v.w;
        e++;
    }
    for (; e + 2 <= end; e += 2) {
        int4 p = *(const int4*)&g_csr[e];
        float w0 = __int_as_float(p.y);
        float w1 = __int_as_float(p.w);
        float4 v0 = h4[(size_t)p.x * 32 + lane];
        float4 v1 = h4[(size_t)p.z * 32 + lane];
        acc.x += w0 * v0.x; acc.y += w0 * v0.y;
        acc.z += w0 * v0.z; acc.w += w0 * v0.w;
        acc.x += w1 * v1.x; acc.y += w1 * v1.y;
        acc.z += w1 * v1.z; acc.w += w1 * v1.w;
    }
    if (e < end) {
        int2 p = g_csr[e];
        float w = __int_as_float(p.y);
        float4 v = h4[(size_t)p.x * 32 + lane];
        acc.x += w * v.x; acc.y += w * v.y;
        acc.z += w * v.z; acc.w += w * v.w;
    }

    if (!do_dot) {
        ((float4*)g_buf)[(size_t)node * 32 + lane] = acc;
    } else {
        acc.x = fmaxf(acc.x, 0.f); acc.y = fmaxf(acc.y, 0.f);
        acc.z = fmaxf(acc.z, 0.f); acc.w = fmaxf(acc.w, 0.f);
        float4 wf = *(const float4*)&Wf[lane * 4];
        float sum = acc.x * wf.x + acc.y * wf.y + acc.z * wf.z + acc.w * wf.w;
        #pragma unroll
        for (int o = 16; o; o >>= 1) sum += __shfl_xor_sync(0xffffffffu, sum, o);
        if (lane == 0) g_hf[node] = sum;
    }
}

// ------------------------------ final layer --------------------------------
__global__ void k_fin(const float* __restrict__ bf, float* __restrict__ out) {
    int i = blockIdx.x * blockDim.x + threadIdx.x;
    if (i >= NN) return;
    float dv = g_dinv[i];
    float acc = dv * dv * g_hf[i] + bf[0];
    int beg = g_rowptr[i], end = g_rowptr[i + 1];
    for (int e = beg; e < end; e++) {
        int2 p = g_csr[e];
        acc += __int_as_float(p.y) * g_hf[p.x];
    }
    out[i] = acc;
}

// ------------------------------- launch ------------------------------------
extern "C" void kernel_launch(void* const* d_in, const int* in_sizes, int n_in,
                              void* d_out, int out_size) {
    const float* x   = (const float*)d_in[0];
    const int*   ei  = (const int*)d_in[1];
    const float* ew  = (const float*)d_in[2];
    const float* Win = (const float*)d_in[3];
    const float* bin = (const float*)d_in[4];
    const float* Wmd = (const float*)d_in[5];
    const float* bmd = (const float*)d_in[6];
    const float* Wfn = (const float*)d_in[7];
    const float* bfn = (const float*)d_in[8];
    float* out = (float*)d_out;

    const int TB = 256;
    const int gN = (NN + TB - 1) / TB;           // 391
    const int gE = (NE + TB - 1) / TB;           // 6250
    const int gG = (NNP + 127) / 128;            // 782
    const int gA = (NN + 7) / 8;                 // 12500 (warp/node)

    k_deg_init<<<gN, TB>>>();                    // 0
    k_deg_acc<<<gE, TB>>>(ei, ew);               // 1
    k_wsplit<<<64, TB>>>(Win, 0);                // 2
    k_wsplit<<<64, TB>>>(Wmd, 1);                // 3
    k_scan1<<<NBLK, 1024>>>();                   // 4
    k_gemm_tc<<<gG, TB>>>(x, 0, 0, 0);           // 5  <-- profiled
    k_scan2<<<1, 128>>>();                       // 6
    k_scan3<<<NBLK, 1024>>>();                   // 7
    k_fill<<<gE, TB>>>(ei, ew);                  // 8

    // layer 1 aggregate
    k_gather<<<gA, TB>>>(bin, 0, nullptr);

    // layer 2
    k_gemm_tc<<<gG, TB>>>(nullptr, 1, 1, 1);
    k_gather<<<gA, TB>>>(bmd, 0, nullptr);

    // layer 3 (+ fused final dot)
    k_gemm_tc<<<gG, TB>>>(nullptr, 1, 1, 1);
    k_gather<<<gA, TB>>>(bmd, 1, Wfn);

    // final aggregation (scalar)
    k_fin<<<gN, TB>>>(bfn, out);
}

// round 10
// speedup vs baseline: 1.5478x; 1.1642x over previous
#include <cuda_runtime.h>
#include <cuda_fp16.h>
#include <cuda_bf16.h>
#include <mma.h>
#include <cstdint>

using namespace nvcuda;

#define NN 100000
#define NNP 100096   // padded to multiple of 128 for unguarded wmma stores
#define NE 1600000
#define F 128
#define NBLK 98      // ceil(NN/1024)
#define AP 40        // A smem pitch (bf16)
#define WP 136       // W smem pitch (bf16)

// -------- scratch (static device globals; no allocations allowed) ----------
__device__ float g_dinv[NN];
__device__ int   g_deg[NN];
__device__ int   g_part[NBLK];
__device__ int   g_rowptr[NN + 1];
__device__ int   g_cursor[NN];
__device__ __align__(16) int2 g_csr[NE];
__device__ __align__(16) __half g_h[(size_t)NNP * F];   // fp16 activations
__device__ float g_buf[(size_t)NNP * F];
__device__ float g_hf[NN];
__device__ __align__(16) __nv_bfloat16 g_Whi[2][F * F];  // [0]=W_in, [1]=W_mid
__device__ __align__(16) __nv_bfloat16 g_Wlo[2][F * F];

// ---------------------------- normalization --------------------------------
__global__ void k_deg_init() {
    int i = blockIdx.x * blockDim.x + threadIdx.x;
    if (i < NN) { g_dinv[i] = 1.0f; g_deg[i] = 0; }
}

__global__ void k_deg_acc(const int* __restrict__ ei,
                          const float* __restrict__ ew) {
    int e = blockIdx.x * blockDim.x + threadIdx.x;
    if (e < NE) {
        int d = ei[NE + e];
        atomicAdd(&g_dinv[d], ew[e]);
        atomicAdd(&g_deg[d], 1);
    }
}

// W split: row-major [k][n] -> hi/lo bf16
__global__ void k_wsplit(const float* __restrict__ W, int which) {
    int i = blockIdx.x * blockDim.x + threadIdx.x;   // 0..16383
    float w = W[i];
    __nv_bfloat16 h = __float2bfloat16(w);
    g_Whi[which][i] = h;
    g_Wlo[which][i] = __float2bfloat16(w - __bfloat162float(h));
}

// --------------------- 3-phase parallel exclusive scan ----------------------
__global__ __launch_bounds__(1024) void k_scan1() {
    __shared__ int s[1024];
    int t = threadIdx.x, i = blockIdx.x * 1024 + t;
    if (i < NN) g_dinv[i] = rsqrtf(g_dinv[i]);
    s[t] = (i < NN) ? g_deg[i] : 0;
    __syncthreads();
    for (int off = 512; off; off >>= 1) {
        if (t < off) s[t] += s[t + off];
        __syncthreads();
    }
    if (t == 0) g_part[blockIdx.x] = s[0];
}

__global__ __launch_bounds__(128) void k_scan2() {
    __shared__ int s[128];
    int t = threadIdx.x;
    int v = (t < NBLK) ? g_part[t] : 0;
    s[t] = v;
    __syncthreads();
    for (int off = 1; off < 128; off <<= 1) {
        int u = (t >= off) ? s[t - off] : 0;
        __syncthreads();
        s[t] += u;
        __syncthreads();
    }
    if (t < NBLK) g_part[t] = s[t] - v;
    if (t == 127) g_rowptr[NN] = s[127];
}

__global__ __launch_bounds__(1024) void k_scan3() {
    __shared__ int s[1024];
    int t = threadIdx.x, i = blockIdx.x * 1024 + t;
    int v = (i < NN) ? g_deg[i] : 0;
    s[t] = v;
    __syncthreads();
    for (int off = 1; off < 1024; off <<= 1) {
        int u = (t >= off) ? s[t - off] : 0;
        __syncthreads();
        s[t] += u;
        __syncthreads();
    }
    if (i < NN) {
        int ex = s[t] - v + g_part[blockIdx.x];
        g_rowptr[i] = ex;
        g_cursor[i] = ex;
    }
}

__global__ void k_fill(const int* __restrict__ ei,
                       const float* __restrict__ ew) {
    int e = blockIdx.x * blockDim.x + threadIdx.x;
    if (e >= NE) return;
    int s = ei[e], d = ei[NE + e];
    int pos = atomicAdd(&g_cursor[d], 1);
    float w = g_dinv[s] * ew[e] * g_dinv[d];
    g_csr[pos] = make_int2(s, __float_as_int(w));
}

// --------------- tensor-core GEMM: wmma bf16 two-term split -----------------
// h[tile, 128] = fp16( act(A) @ W ), via Ahi*Whi + Ahi*Wlo + Alo*Whi (fp32 acc)
__global__ __launch_bounds__(256) void k_gemm_tc(const float* __restrict__ Aext,
                                                 int widx, int use_gbuf,
                                                 int relu_in) {
    const float* __restrict__ A = use_gbuf ? (const float*)g_buf : Aext;
    __shared__ __nv_bfloat16 Ah[128 * AP];
    __shared__ __nv_bfloat16 Al[128 * AP];
    __shared__ __nv_bfloat16 Wh[32 * WP];
    __shared__ __nv_bfloat16 Wl[32 * WP];
    int tid = threadIdx.x;
    int wid = tid >> 5;
    int row0 = blockIdx.x * 128;
    const __nv_bfloat16* __restrict__ Whig = g_Whi[widx];
    const __nv_bfloat16* __restrict__ Wlog = g_Wlo[widx];

    wmma::fragment<wmma::accumulator, 16, 16, 16, float> acc[8];
    #pragma unroll
    for (int c = 0; c < 8; c++) wmma::fill_fragment(acc[c], 0.0f);

    for (int kc = 0; kc < F; kc += 32) {
        // A chunk 128x32 fp32 -> split bf16 smem (1024 float4, 4/thread)
        #pragma unroll
        for (int i = 0; i < 4; i++) {
            int idx = tid + i * 256;
            int r = idx >> 3, c4 = idx & 7;
            int row = row0 + r;
            float4 v = make_float4(0.f, 0.f, 0.f, 0.f);
            if (row < NN) v = *(const float4*)&A[(size_t)row * F + kc + c4 * 4];
            if (relu_in) {
                v.x = fmaxf(v.x, 0.f); v.y = fmaxf(v.y, 0.f);
                v.z = fmaxf(v.z, 0.f); v.w = fmaxf(v.w, 0.f);
            }
            __nv_bfloat162 h01 = __floats2bfloat162_rn(v.x, v.y);
            __nv_bfloat162 h23 = __floats2bfloat162_rn(v.z, v.w);
            *(__nv_bfloat162*)&Ah[r * AP + c4 * 4]     = h01;
            *(__nv_bfloat162*)&Ah[r * AP + c4 * 4 + 2] = h23;
            __nv_bfloat162 l01 = __floats2bfloat162_rn(v.x - __low2float(h01),
                                                       v.y - __high2float(h01));
            __nv_bfloat162 l23 = __floats2bfloat162_rn(v.z - __low2float(h23),
                                                       v.w - __high2float(h23));
            *(__nv_bfloat162*)&Al[r * AP + c4 * 4]     = l01;
            *(__nv_bfloat162*)&Al[r * AP + c4 * 4 + 2] = l23;
        }
        // W chunk 32x128 bf16 copy (512 int4 per image, 2/thread)
        #pragma unroll
        for (int i = 0; i < 2; i++) {
            int idx = tid + i * 256;
            int k = idx >> 4, c16 = idx & 15;
            *(int4*)&Wh[k * WP + c16 * 8] =
                *(const int4*)&Whig[(kc + k) * F + c16 * 8];
            *(int4*)&Wl[k * WP + c16 * 8] =
                *(const int4*)&Wlog[(kc + k) * F + c16 * 8];
        }
        __syncthreads();

        #pragma unroll
        for (int ks = 0; ks < 32; ks += 16) {
            wmma::fragment<wmma::matrix_a, 16, 16, 16, __nv_bfloat16,
                           wmma::row_major> ah, al;
            wmma::load_matrix_sync(ah, &Ah[(wid * 16) * AP + ks], AP);
            wmma::load_matrix_sync(al, &Al[(wid * 16) * AP + ks], AP);
            #pragma unroll
            for (int c = 0; c < 8; c++) {
                wmma::fragment<wmma::matrix_b, 16, 16, 16, __nv_bfloat16,
                               wmma::row_major> bh, bl;
                wmma::load_matrix_sync(bh, &Wh[ks * WP + c * 16], WP);
                wmma::load_matrix_sync(bl, &Wl[ks * WP + c * 16], WP);
                wmma::mma_sync(acc[c], ah, bh, acc[c]);
                wmma::mma_sync(acc[c], ah, bl, acc[c]);
                wmma::mma_sync(acc[c], al, bh, acc[c]);
            }
        }
        __syncthreads();
    }
    // store 16x128 per warp as fp16; f32 and f16 accumulator fragments share
    // the same per-thread (row,col) element order (PTX mma C-layout).
    __half* outp = &g_h[(size_t)(row0 + wid * 16) * F];
    #pragma unroll
    for (int c = 0; c < 8; c++) {
        wmma::fragment<wmma::accumulator, 16, 16, 16, __half> hacc;
        #pragma unroll
        for (int i = 0; i < 8; i++) hacc.x[i] = __float2half(acc[c].x[i]);
        wmma::store_matrix_sync(outp + c * 16, hacc, F, wmma::mem_row_major);
    }
}

// ----------------------- aggregation: CSR gather ----------------------------
// Warp per node, 4 features per lane (one uint2 = 4 fp16 per load).
__global__ __launch_bounds__(256) void k_gather(const float* __restrict__ b,
                                                int do_dot,
                                                const float* __restrict__ Wf) {
    int node = blockIdx.x * 8 + (threadIdx.x >> 5);
    int lane = threadIdx.x & 31;
    if (node >= NN) return;
    const uint2* __restrict__ h2 = (const uint2*)g_h;

    float dv = g_dinv[node];
    float s2 = dv * dv;
    uint2 hv = h2[(size_t)node * 32 + lane];
    float2 f0 = __half22float2(*(__half2*)&hv.x);
    float2 f1 = __half22float2(*(__half2*)&hv.y);
    float4 bv = *(const float4*)&b[lane * 4];
    float4 acc;
    acc.x = s2 * f0.x + bv.x; acc.y = s2 * f0.y + bv.y;
    acc.z = s2 * f1.x + bv.z; acc.w = s2 * f1.y + bv.w;

    int beg = g_rowptr[node], end = g_rowptr[node + 1];
    int e = beg;
    if ((e & 1) && e < end) {                    // peel to 16B alignment
        int2 p = g_csr[e];
        float w = __int_as_float(p.y);
        uint2 v = h2[(size_t)p.x * 32 + lane];
        float2 a0 = __half22float2(*(__half2*)&v.x);
        float2 a1 = __half22float2(*(__half2*)&v.y);
        acc.x += w * a0.x; acc.y += w * a0.y;
        acc.z += w * a1.x; acc.w += w * a1.y;
        e++;
    }
    for (; e + 2 <= end; e += 2) {
        int4 p = *(const int4*)&g_csr[e];        // two (src,w) pairs, aligned
        float w0 = __int_as_float(p.y);
        float w1 = __int_as_float(p.w);
        uint2 v0 = h2[(size_t)p.x * 32 + lane];
        uint2 v1 = h2[(size_t)p.z * 32 + lane];
        float2 a0 = __half22float2(*(__half2*)&v0.x);
        float2 a1 = __half22float2(*(__half2*)&v0.y);
        float2 c0 = __half22float2(*(__half2*)&v1.x);
        float2 c1 = __half22float2(*(__half2*)&v1.y);
        acc.x += w0 * a0.x; acc.y += w0 * a0.y;
        acc.z += w0 * a1.x; acc.w += w0 * a1.y;
        acc.x += w1 * c0.x; acc.y += w1 * c0.y;
        acc.z += w1 * c1.x; acc.w += w1 * c1.y;
    }
    if (e < end) {
        int2 p = g_csr[e];
        float w = __int_as_float(p.y);
        uint2 v = h2[(size_t)p.x * 32 + lane];
        float2 a0 = __half22float2(*(__half2*)&v.x);
        float2 a1 = __half22float2(*(__half2*)&v.y);
        acc.x += w * a0.x; acc.y += w * a0.y;
        acc.z += w * a1.x; acc.w += w * a1.y;
    }

    if (!do_dot) {
        ((float4*)g_buf)[(size_t)node * 32 + lane] = acc;
    } else {
        acc.x = fmaxf(acc.x, 0.f); acc.y = fmaxf(acc.y, 0.f);
        acc.z = fmaxf(acc.z, 0.f); acc.w = fmaxf(acc.w, 0.f);
        float4 wf = *(const float4*)&Wf[lane * 4];
        float sum = acc.x * wf.x + acc.y * wf.y + acc.z * wf.z + acc.w * wf.w;
        #pragma unroll
        for (int o = 16; o; o >>= 1) sum += __shfl_xor_sync(0xffffffffu, sum, o);
        if (lane == 0) g_hf[node] = sum;
    }
}

// ------------------------------ final layer --------------------------------
__global__ void k_fin(const float* __restrict__ bf, float* __restrict__ out) {
    int i = blockIdx.x * blockDim.x + threadIdx.x;
    if (i >= NN) return;
    float dv = g_dinv[i];
    float acc = dv * dv * g_hf[i] + bf[0];
    int beg = g_rowptr[i], end = g_rowptr[i + 1];
    for (int e = beg; e < end; e++) {
        int2 p = g_csr[e];
        acc += __int_as_float(p.y) * g_hf[p.x];
    }
    out[i] = acc;
}

// ------------------------------- launch ------------------------------------
extern "C" void kernel_launch(void* const* d_in, const int* in_sizes, int n_in,
                              void* d_out, int out_size) {
    const float* x   = (const float*)d_in[0];
    const int*   ei  = (const int*)d_in[1];
    const float* ew  = (const float*)d_in[2];
    const float* Win = (const float*)d_in[3];
    const float* bin = (const float*)d_in[4];
    const float* Wmd = (const float*)d_in[5];
    const float* bmd = (const float*)d_in[6];
    const float* Wfn = (const float*)d_in[7];
    const float* bfn = (const float*)d_in[8];
    float* out = (float*)d_out;

    const int TB = 256;
    const int gN = (NN + TB - 1) / TB;           // 391
    const int gE = (NE + TB - 1) / TB;           // 6250
    const int gG = (NNP + 127) / 128;            // 782
    const int gA = (NN + 7) / 8;                 // 12500 (warp/node)

    k_deg_init<<<gN, TB>>>();                    // 0
    k_deg_acc<<<gE, TB>>>(ei, ew);               // 1
    k_wsplit<<<64, TB>>>(Win, 0);                // 2
    k_wsplit<<<64, TB>>>(Wmd, 1);                // 3
    k_scan1<<<NBLK, 1024>>>();                   // 4
    k_gemm_tc<<<gG, TB>>>(x, 0, 0, 0);           // 5
    k_scan2<<<1, 128>>>();                       // 6
    k_scan3<<<NBLK, 1024>>>();                   // 7
    k_fill<<<gE, TB>>>(ei, ew);                  // 8

    // layer 1 aggregate
    k_gather<<<gA, TB>>>(bin, 0, nullptr);

    // layer 2
    k_gemm_tc<<<gG, TB>>>(nullptr, 1, 1, 1);
    k_gather<<<gA, TB>>>(bmd, 0, nullptr);

    // layer 3 (+ fused final dot)
    k_gemm_tc<<<gG, TB>>>(nullptr, 1, 1, 1);
    k_gather<<<gA, TB>>>(bmd, 1, Wfn);

    // final aggregation (scalar)
    k_fin<<<gN, TB>>>(bfn, out);
}

// round 11
// speedup vs baseline: 2.1110x; 1.3639x over previous
#include <cuda_runtime.h>
#include <cuda_fp16.h>
#include <cstdint>
#include <mma.h>

using namespace nvcuda;

#define NN 100000
#define NNP 100096   // padded to multiple of 128 for unguarded wmma stores
#define NE 1600000
#define F 128
#define NBLK 98      // ceil(NN/1024)
#define AP 40        // A smem pitch (fp16)
#define WP 136       // W smem pitch (fp16)

// -------- scratch (static device globals; no allocations allowed) ----------
__device__ float g_dinv[NN];
__device__ int   g_deg[NN];
__device__ int   g_part[NBLK];
__device__ int   g_rowptr[NN + 1];
__device__ int   g_cursor[NN];
__device__ __align__(16) int2 g_csr[NE];
__device__ __align__(16) __half g_h[(size_t)NNP * F];     // GEMM out (fp16)
__device__ __align__(16) __half g_buf[(size_t)NNP * F];   // relu(agg) (fp16)
__device__ __align__(16) __half g_x16[(size_t)NN * F];    // fp16 copy of x
__device__ float g_hf[NN];
__device__ __align__(16) __half g_Whi[2][F * F];  // [0]=W_in, [1]=W_mid
__device__ __align__(16) __half g_Wlo[2][F * F];

// ---------------------------- normalization --------------------------------
__global__ void k_deg_init() {
    int i = blockIdx.x * blockDim.x + threadIdx.x;
    if (i < NN) { g_dinv[i] = 1.0f; g_deg[i] = 0; }
}

__global__ void k_deg_acc(const int* __restrict__ ei,
                          const float* __restrict__ ew) {
    int e = blockIdx.x * blockDim.x + threadIdx.x;
    if (e < NE) {
        int d = ei[NE + e];
        atomicAdd(&g_dinv[d], ew[e]);
        atomicAdd(&g_deg[d], 1);
    }
}

// x fp32 -> fp16 (8 elements/thread)
__global__ void k_x2h(const float* __restrict__ x) {
    int i = blockIdx.x * blockDim.x + threadIdx.x;   // 0 .. NN*F/8-1
    if (i >= NN * (F / 8)) return;
    float4 a = *(const float4*)&x[(size_t)i * 8];
    float4 b = *(const float4*)&x[(size_t)i * 8 + 4];
    __half2 h0 = __float22half2_rn(make_float2(a.x, a.y));
    __half2 h1 = __float22half2_rn(make_float2(a.z, a.w));
    __half2 h2 = __float22half2_rn(make_float2(b.x, b.y));
    __half2 h3 = __float22half2_rn(make_float2(b.z, b.w));
    uint4 o;
    o.x = *(uint32_t*)&h0; o.y = *(uint32_t*)&h1;
    o.z = *(uint32_t*)&h2; o.w = *(uint32_t*)&h3;
    *(uint4*)&g_x16[(size_t)i * 8] = o;
}

// W split: row-major [k][n] -> fp16 hi + fp16 lo (~22 bits total)
__global__ void k_wsplit(const float* __restrict__ W, int which) {
    int i = blockIdx.x * blockDim.x + threadIdx.x;   // 0..16383
    float w = W[i];
    __half h = __float2half(w);
    g_Whi[which][i] = h;
    g_Wlo[which][i] = __float2half(w - __half2float(h));
}

// --------------------- 3-phase parallel exclusive scan ----------------------
__global__ __launch_bounds__(1024) void k_scan1() {
    __shared__ int s[1024];
    int t = threadIdx.x, i = blockIdx.x * 1024 + t;
    if (i < NN) g_dinv[i] = rsqrtf(g_dinv[i]);
    s[t] = (i < NN) ? g_deg[i] : 0;
    __syncthreads();
    for (int off = 512; off; off >>= 1) {
        if (t < off) s[t] += s[t + off];
        __syncthreads();
    }
    if (t == 0) g_part[blockIdx.x] = s[0];
}

__global__ __launch_bounds__(128) void k_scan2() {
    __shared__ int s[128];
    int t = threadIdx.x;
    int v = (t < NBLK) ? g_part[t] : 0;
    s[t] = v;
    __syncthreads();
    for (int off = 1; off < 128; off <<= 1) {
        int u = (t >= off) ? s[t - off] : 0;
        __syncthreads();
        s[t] += u;
        __syncthreads();
    }
    if (t < NBLK) g_part[t] = s[t] - v;
    if (t == 127) g_rowptr[NN] = s[127];
}

__global__ __launch_bounds__(1024) void k_scan3() {
    __shared__ int s[1024];
    int t = threadIdx.x, i = blockIdx.x * 1024 + t;
    int v = (i < NN) ? g_deg[i] : 0;
    s[t] = v;
    __syncthreads();
    for (int off = 1; off < 1024; off <<= 1) {
        int u = (t >= off) ? s[t - off] : 0;
        __syncthreads();
        s[t] += u;
        __syncthreads();
    }
    if (i < NN) {
        int ex = s[t] - v + g_part[blockIdx.x];
        g_rowptr[i] = ex;
        g_cursor[i] = ex;
    }
}

__global__ void k_fill(const int* __restrict__ ei,
                       const float* __restrict__ ew) {
    int e = blockIdx.x * blockDim.x + threadIdx.x;
    if (e >= NE) return;
    int s = ei[e], d = ei[NE + e];
    int pos = atomicAdd(&g_cursor[d], 1);
    float w = g_dinv[s] * ew[e] * g_dinv[d];
    g_csr[pos] = make_int2(s, __float_as_int(w));
}

// ------------- tensor-core GEMM: fp16 A x (fp16 hi+lo) W -------------------
// h[tile,128] = fp16( A @ W ),  D = A*Whi + A*Wlo  (fp32 accum)
__global__ __launch_bounds__(256) void k_gemm_tc(const __half* __restrict__ A,
                                                 int widx) {
    __shared__ __half Ah[128 * AP];
    __shared__ __half Wh[32 * WP];
    __shared__ __half Wl[32 * WP];
    int tid = threadIdx.x;
    int wid = tid >> 5;
    int row0 = blockIdx.x * 128;
    const __half* __restrict__ Whig = g_Whi[widx];
    const __half* __restrict__ Wlog = g_Wlo[widx];

    wmma::fragment<wmma::accumulator, 16, 16, 16, float> acc[8];
    #pragma unroll
    for (int c = 0; c < 8; c++) wmma::fill_fragment(acc[c], 0.0f);

    for (int kc = 0; kc < F; kc += 32) {
        // A chunk 128x32 fp16 = 512 uint4 (2/thread), plain copy
        #pragma unroll
        for (int i = 0; i < 2; i++) {
            int idx = tid + i * 256;
            int r = idx >> 2, q = idx & 3;            // q: 8-half group
            int row = row0 + r;
            uint4 v = make_uint4(0u, 0u, 0u, 0u);
            if (row < NN) v = *(const uint4*)&A[(size_t)row * F + kc + q * 8];
            *(uint4*)&Ah[r * AP + q * 8] = v;
        }
        // W chunk 32x128 fp16 copy (512 uint4 per image, 2/thread)
        #pragma unroll
        for (int i = 0; i < 2; i++) {
            int idx = tid + i * 256;
            int k = idx >> 4, c16 = idx & 15;
            *(uint4*)&Wh[k * WP + c16 * 8] =
                *(const uint4*)&Whig[(kc + k) * F + c16 * 8];
            *(uint4*)&Wl[k * WP + c16 * 8] =
                *(const uint4*)&Wlog[(kc + k) * F + c16 * 8];
        }
        __syncthreads();

        #pragma unroll
        for (int ks = 0; ks < 32; ks += 16) {
            wmma::fragment<wmma::matrix_a, 16, 16, 16, __half,
                           wmma::row_major> a;
            wmma::load_matrix_sync(a, &Ah[(wid * 16) * AP + ks], AP);
            #pragma unroll
            for (int c = 0; c < 8; c++) {
                wmma::fragment<wmma::matrix_b, 16, 16, 16, __half,
                               wmma::row_major> bh, bl;
                wmma::load_matrix_sync(bh, &Wh[ks * WP + c * 16], WP);
                wmma::load_matrix_sync(bl, &Wl[ks * WP + c * 16], WP);
                wmma::mma_sync(acc[c], a, bh, acc[c]);
                wmma::mma_sync(acc[c], a, bl, acc[c]);
            }
        }
        __syncthreads();
    }
    // store 16x128 per warp as fp16 (f32/f16 acc fragments share layout)
    __half* outp = &g_h[(size_t)(row0 + wid * 16) * F];
    #pragma unroll
    for (int c = 0; c < 8; c++) {
        wmma::fragment<wmma::accumulator, 16, 16, 16, __half> hacc;
        #pragma unroll
        for (int i = 0; i < 8; i++) hacc.x[i] = __float2half(acc[c].x[i]);
        wmma::store_matrix_sync(outp + c * 16, hacc, F, wmma::mem_row_major);
    }
}

// ----------------------- aggregation: CSR gather ----------------------------
// Warp per node, 4 features per lane. Output: relu(agg) -> fp16 g_buf,
// or (do_dot) g_hf[n] = relu(agg) . Wf.
__global__ __launch_bounds__(256) void k_gather(const float* __restrict__ b,
                                                int do_dot,
                                                const float* __restrict__ Wf) {
    int node = blockIdx.x * 8 + (threadIdx.x >> 5);
    int lane = threadIdx.x & 31;
    if (node >= NN) return;
    const uint2* __restrict__ h2 = (const uint2*)g_h;

    float dv = g_dinv[node];
    float s2 = dv * dv;
    uint2 hv = h2[(size_t)node * 32 + lane];
    float2 f0 = __half22float2(*(__half2*)&hv.x);
    float2 f1 = __half22float2(*(__half2*)&hv.y);
    float4 bv = *(const float4*)&b[lane * 4];
    float4 acc;
    acc.x = s2 * f0.x + bv.x; acc.y = s2 * f0.y + bv.y;
    acc.z = s2 * f1.x + bv.z; acc.w = s2 * f1.y + bv.w;

    int beg = g_rowptr[node], end = g_rowptr[node + 1];
    int e = beg;
    if ((e & 1) && e < end) {                    // peel to 16B alignment
        int2 p = g_csr[e];
        float w = __int_as_float(p.y);
        uint2 v = h2[(size_t)p.x * 32 + lane];
        float2 a0 = __half22float2(*(__half2*)&v.x);
        float2 a1 = __half22float2(*(__half2*)&v.y);
        acc.x += w * a0.x; acc.y += w * a0.y;
        acc.z += w * a1.x; acc.w += w * a1.y;
        e++;
    }
    for (; e + 2 <= end; e += 2) {
        int4 p = *(const int4*)&g_csr[e];        // two (src,w) pairs, aligned
        float w0 = __int_as_float(p.y);
        float w1 = __int_as_float(p.w);
        uint2 v0 = h2[(size_t)p.x * 32 + lane];
        uint2 v1 = h2[(size_t)p.z * 32 + lane];
        float2 a0 = __half22float2(*(__half2*)&v0.x);
        float2 a1 = __half22float2(*(__half2*)&v0.y);
        float2 c0 = __half22float2(*(__half2*)&v1.x);
        float2 c1 = __half22float2(*(__half2*)&v1.y);
        acc.x += w0 * a0.x; acc.y += w0 * a0.y;
        acc.z += w0 * a1.x; acc.w += w0 * a1.y;
        acc.x += w1 * c0.x; acc.y += w1 * c0.y;
        acc.z += w1 * c1.x; acc.w += w1 * c1.y;
    }
    if (e < end) {
        int2 p = g_csr[e];
        float w = __int_as_float(p.y);
        uint2 v = h2[(size_t)p.x * 32 + lane];
        float2 a0 = __half22float2(*(__half2*)&v.x);
        float2 a1 = __half22float2(*(__half2*)&v.y);
        acc.x += w * a0.x; acc.y += w * a0.y;
        acc.z += w * a1.x; acc.w += w * a1.y;
    }

    // relu fused here (both paths need it)
    acc.x = fmaxf(acc.x, 0.f); acc.y = fmaxf(acc.y, 0.f);
    acc.z = fmaxf(acc.z, 0.f); acc.w = fmaxf(acc.w, 0.f);

    if (!do_dot) {
        __half2 o0 = __float22half2_rn(make_float2(acc.x, acc.y));
        __half2 o1 = __float22half2_rn(make_float2(acc.z, acc.w));
        uint2 o;
        o.x = *(uint32_t*)&o0; o.y = *(uint32_t*)&o1;
        ((uint2*)g_buf)[(size_t)node * 32 + lane] = o;
    } else {
        float4 wf = *(const float4*)&Wf[lane * 4];
        float sum = acc.x * wf.x + acc.y * wf.y + acc.z * wf.z + acc.w * wf.w;
        #pragma unroll
        for (int o = 16; o; o >>= 1) sum += __shfl_xor_sync(0xffffffffu, sum, o);
        if (lane == 0) g_hf[node] = sum;
    }
}

// ------------------------------ final layer --------------------------------
__global__ void k_fin(const float* __restrict__ bf, float* __restrict__ out) {
    int i = blockIdx.x * blockDim.x + threadIdx.x;
    if (i >= NN) return;
    float dv = g_dinv[i];
    float acc = dv * dv * g_hf[i] + bf[0];
    int beg = g_rowptr[i], end = g_rowptr[i + 1];
    for (int e = beg; e < end; e++) {
        int2 p = g_csr[e];
        acc += __int_as_float(p.y) * g_hf[p.x];
    }
    out[i] = acc;
}

// ------------------------------- launch ------------------------------------
extern "C" void kernel_launch(void* const* d_in, const int* in_sizes, int n_in,
                              void* d_out, int out_size) {
    const float* x   = (const float*)d_in[0];
    const int*   ei  = (const int*)d_in[1];
    const float* ew  = (const float*)d_in[2];
    const float* Win = (const float*)d_in[3];
    const float* bin = (const float*)d_in[4];
    const float* Wmd = (const float*)d_in[5];
    const float* bmd = (const float*)d_in[6];
    const float* Wfn = (const float*)d_in[7];
    const float* bfn = (const float*)d_in[8];
    float* out = (float*)d_out;

    __half* x16;
    cudaGetSymbolAddress((void**)&x16, g_x16);
    __half* buf16;
    cudaGetSymbolAddress((void**)&buf16, g_buf);

    const int TB = 256;
    const int gN = (NN + TB - 1) / TB;           // 391
    const int gE = (NE + TB - 1) / TB;           // 6250
    const int gG = (NNP + 127) / 128;            // 782
    const int gA = (NN + 7) / 8;                 // 12500 (warp/node)
    const int gX = (NN * (F / 8) + TB - 1) / TB; // 6250

    k_deg_init<<<gN, TB>>>();                    // 0
    k_deg_acc<<<gE, TB>>>(ei, ew);               // 1
    k_x2h<<<gX, TB>>>(x);                        // 2
    k_wsplit<<<64, TB>>>(Win, 0);                // 3
    k_wsplit<<<64, TB>>>(Wmd, 1);                // 4
    k_gemm_tc<<<gG, TB>>>(x16, 0);               // 5  <-- profiled
    k_scan1<<<NBLK, 1024>>>();                   // 6
    k_scan2<<<1, 128>>>();                       // 7
    k_scan3<<<NBLK, 1024>>>();                   // 8
    k_fill<<<gE, TB>>>(ei, ew);                  // 9

    // layer 1 aggregate (writes relu'd fp16 buf)
    k_gather<<<gA, TB>>>(bin, 0, nullptr);

    // layer 2
    k_gemm_tc<<<gG, TB>>>(buf16, 1);
    k_gather<<<gA, TB>>>(bmd, 0, nullptr);

    // layer 3 (+ fused final dot)
    k_gemm_tc<<<gG, TB>>>(buf16, 1);
    k_gather<<<gA, TB>>>(bmd, 1, Wfn);

    // final aggregation (scalar)
    k_fin<<<gN, TB>>>(bfn, out);
}

// round 12
// speedup vs baseline: 2.1660x; 1.0261x over previous
#include <cuda_runtime.h>
#include <cuda_fp16.h>
#include <cstdint>
#include <mma.h>

using namespace nvcuda;

#define NN 100000
#define NNP 100096   // padded to multiple of 128 for unguarded wmma stores
#define NE 1600000
#define F 128
#define NBLK 98      // ceil(NN/1024)
#define GP 136       // GEMM smem pitch (fp16)
#define SMEM_G (3 * 128 * GP * 2)   // 104448 B: A + Whi + Wlo
#define GX 6250      // blocks for x->fp16 (NN*F/8/256)

// -------- scratch (static device globals; no allocations allowed) ----------
__device__ float g_dinv[NN];
__device__ int   g_deg[NN];
__device__ unsigned long long g_desc[NBLK];   // lookback: status<<32 | value
__device__ int   g_rowptr[NN + 1];
__device__ int   g_cursor[NN];
__device__ __align__(16) int2 g_csr[NE];
__device__ __align__(16) __half g_h[(size_t)NNP * F];     // GEMM out (fp16)
__device__ __align__(16) __half g_buf[(size_t)NNP * F];   // relu(agg) (fp16)
__device__ __align__(16) __half g_x16[(size_t)NN * F];    // fp16 copy of x
__device__ float g_hf[NN];
__device__ __align__(16) __half g_Whi[2][F * F];  // [0]=W_in, [1]=W_mid
__device__ __align__(16) __half g_Wlo[2][F * F];

// ---------------------------- normalization --------------------------------
__global__ void k_deg_init() {
    int i = blockIdx.x * blockDim.x + threadIdx.x;
    if (i < NN) { g_dinv[i] = 1.0f; g_deg[i] = 0; }
    if (i < NBLK) g_desc[i] = 0ull;              // reset lookback state
}

__global__ void k_deg_acc(const int* __restrict__ ei,
                          const float* __restrict__ ew) {
    int e = blockIdx.x * blockDim.x + threadIdx.x;
    if (e < NE) {
        int d = ei[NE + e];
        atomicAdd(&g_dinv[d], ew[e]);
        atomicAdd(&g_deg[d], 1);
    }
}

// merged converts: blocks [0,GX) x->fp16; blocks [GX,GX+128) W hi/lo split
__global__ void k_cvt(const float* __restrict__ x,
                      const float* __restrict__ Win,
                      const float* __restrict__ Wmd) {
    int bid = blockIdx.x;
    if (bid < GX) {
        int i = bid * 256 + threadIdx.x;          // 8-elt unit
        if (i >= NN * (F / 8)) return;
        float4 a = *(const float4*)&x[(size_t)i * 8];
        float4 b = *(const float4*)&x[(size_t)i * 8 + 4];
        __half2 h0 = __float22half2_rn(make_float2(a.x, a.y));
        __half2 h1 = __float22half2_rn(make_float2(a.z, a.w));
        __half2 h2 = __float22half2_rn(make_float2(b.x, b.y));
        __half2 h3 = __float22half2_rn(make_float2(b.z, b.w));
        uint4 o;
        o.x = *(uint32_t*)&h0; o.y = *(uint32_t*)&h1;
        o.z = *(uint32_t*)&h2; o.w = *(uint32_t*)&h3;
        *(uint4*)&g_x16[(size_t)i * 8] = o;
    } else {
        int r = bid - GX;                         // 0..127
        int which = r >> 6;                       // 0=W_in, 1=W_mid
        int i = (r & 63) * 256 + threadIdx.x;     // 0..16383
        const float* W = which ? Wmd : Win;
        float w = W[i];
        __half h = __float2half(w);
        g_Whi[which][i] = h;
        g_Wlo[which][i] = __float2half(w - __half2float(h));
    }
}

// ------------- single-pass exclusive scan (decoupled lookback) --------------
// grid = NBLK (98) blocks, all co-resident on 148 SMs -> spin is safe.
__global__ __launch_bounds__(1024) void k_scan() {
    __shared__ int s[1024];
    __shared__ int sprefix;
    int t = threadIdx.x, b = blockIdx.x, i = b * 1024 + t;
    if (i < NN) g_dinv[i] = rsqrtf(g_dinv[i]);   // deg >= 1 always
    int v = (i < NN) ? g_deg[i] : 0;
    s[t] = v;
    __syncthreads();
    for (int off = 1; off < 1024; off <<= 1) {   // Hillis-Steele inclusive
        int u = (t >= off) ? s[t - off] : 0;
        __syncthreads();
        s[t] += u;
        __syncthreads();
    }
    if (t == 0) {
        unsigned agg = (unsigned)s[1023];
        atomicExch(&g_desc[b], (1ull << 32) | agg);   // publish aggregate
        unsigned sum = 0;
        for (int j = b - 1; j >= 0;) {
            unsigned long long d = atomicAdd(&g_desc[j], 0ull);
            unsigned st = (unsigned)(d >> 32);
            if (st == 0) continue;                    // not yet published
            sum += (unsigned)d;
            if (st == 2) break;                       // inclusive prefix
            j--;                                      // aggregate: keep going
        }
        atomicExch(&g_desc[b], (2ull << 32) | (sum + agg));
        sprefix = (int)sum;
        if (b == NBLK - 1) g_rowptr[NN] = (int)(sum + agg);
    }
    __syncthreads();
    if (i < NN) {
        int ex = s[t] - v + sprefix;
        g_rowptr[i] = ex;
        g_cursor[i] = ex;
    }
}

__global__ void k_fill(const int* __restrict__ ei,
                       const float* __restrict__ ew) {
    int e = blockIdx.x * blockDim.x + threadIdx.x;
    if (e >= NE) return;
    int s = ei[e], d = ei[NE + e];
    int pos = atomicAdd(&g_cursor[d], 1);
    float w = g_dinv[s] * ew[e] * g_dinv[d];
    g_csr[pos] = make_int2(s, __float_as_int(w));
}

// ------------- tensor-core GEMM: fp16 A x (fp16 hi+lo) W -------------------
// Full A tile (128x128) + full W images resident in dynamic smem; single sync.
__global__ __launch_bounds__(256) void k_gemm_tc(const __half* __restrict__ A,
                                                 int widx) {
    extern __shared__ __half sm[];
    __half* Ah = sm;                    // 128 x GP
    __half* Wh = sm + 128 * GP;
    __half* Wl = Wh + 128 * GP;
    int tid = threadIdx.x;
    int wid = tid >> 5;
    int row0 = blockIdx.x * 128;
    const __half* __restrict__ Whig = g_Whi[widx];
    const __half* __restrict__ Wlog = g_Wlo[widx];

    // A: 2048 uint4 (8/thread)
    #pragma unroll
    for (int i = 0; i < 8; i++) {
        int idx = tid + i * 256;
        int r = idx >> 4, q = idx & 15;
        int row = row0 + r;
        uint4 v = make_uint4(0u, 0u, 0u, 0u);
        if (row < NN) v = *(const uint4*)&A[(size_t)row * F + q * 8];
        *(uint4*)&Ah[r * GP + q * 8] = v;
    }
    // W: 2048 uint4 per image (8/thread each)
    #pragma unroll
    for (int i = 0; i < 8; i++) {
        int idx = tid + i * 256;
        int k = idx >> 4, q = idx & 15;
        *(uint4*)&Wh[k * GP + q * 8] = *(const uint4*)&Whig[k * F + q * 8];
        *(uint4*)&Wl[k * GP + q * 8] = *(const uint4*)&Wlog[k * F + q * 8];
    }
    __syncthreads();

    wmma::fragment<wmma::accumulator, 16, 16, 16, float> acc[8];
    #pragma unroll
    for (int c = 0; c < 8; c++) wmma::fill_fragment(acc[c], 0.0f);

    #pragma unroll
    for (int ks = 0; ks < 8; ks++) {
        wmma::fragment<wmma::matrix_a, 16, 16, 16, __half, wmma::row_major> a;
        wmma::load_matrix_sync(a, &Ah[(wid * 16) * GP + ks * 16], GP);
        #pragma unroll
        for (int c = 0; c < 8; c++) {
            wmma::fragment<wmma::matrix_b, 16, 16, 16, __half,
                           wmma::row_major> bh, bl;
            wmma::load_matrix_sync(bh, &Wh[(ks * 16) * GP + c * 16], GP);
            wmma::load_matrix_sync(bl, &Wl[(ks * 16) * GP + c * 16], GP);
            wmma::mma_sync(acc[c], a, bh, acc[c]);
            wmma::mma_sync(acc[c], a, bl, acc[c]);
        }
    }
    // store 16x128 per warp as fp16 (f32/f16 acc fragments share layout)
    __half* outp = &g_h[(size_t)(row0 + wid * 16) * F];
    #pragma unroll
    for (int c = 0; c < 8; c++) {
        wmma::fragment<wmma::accumulator, 16, 16, 16, __half> hacc;
        #pragma unroll
        for (int i = 0; i < 8; i++) hacc.x[i] = __float2half(acc[c].x[i]);
        wmma::store_matrix_sync(outp + c * 16, hacc, F, wmma::mem_row_major);
    }
}

// ----------------------- aggregation: CSR gather ----------------------------
__global__ __launch_bounds__(256) void k_gather(const float* __restrict__ b,
                                                int do_dot,
                                                const float* __restrict__ Wf) {
    int node = blockIdx.x * 8 + (threadIdx.x >> 5);
    int lane = threadIdx.x & 31;
    if (node >= NN) return;
    const uint2* __restrict__ h2 = (const uint2*)g_h;

    float dv = g_dinv[node];
    float s2 = dv * dv;
    uint2 hv = h2[(size_t)node * 32 + lane];
    float2 f0 = __half22float2(*(__half2*)&hv.x);
    float2 f1 = __half22float2(*(__half2*)&hv.y);
    float4 bv = *(const float4*)&b[lane * 4];
    float4 acc;
    acc.x = s2 * f0.x + bv.x; acc.y = s2 * f0.y + bv.y;
    acc.z = s2 * f1.x + bv.z; acc.w = s2 * f1.y + bv.w;

    int beg = g_rowptr[node], end = g_rowptr[node + 1];
    int e = beg;
    if ((e & 1) && e < end) {                    // peel to 16B alignment
        int2 p = g_csr[e];
        float w = __int_as_float(p.y);
        uint2 v = h2[(size_t)p.x * 32 + lane];
        float2 a0 = __half22float2(*(__half2*)&v.x);
        float2 a1 = __half22float2(*(__half2*)&v.y);
        acc.x += w * a0.x; acc.y += w * a0.y;
        acc.z += w * a1.x; acc.w += w * a1.y;
        e++;
    }
    for (; e + 2 <= end; e += 2) {
        int4 p = *(const int4*)&g_csr[e];        // two (src,w) pairs, aligned
        float w0 = __int_as_float(p.y);
        float w1 = __int_as_float(p.w);
        uint2 v0 = h2[(size_t)p.x * 32 + lane];
        uint2 v1 = h2[(size_t)p.z * 32 + lane];
        float2 a0 = __half22float2(*(__half2*)&v0.x);
        float2 a1 = __half22float2(*(__half2*)&v0.y);
        float2 c0 = __half22float2(*(__half2*)&v1.x);
        float2 c1 = __half22float2(*(__half2*)&v1.y);
        acc.x += w0 * a0.x; acc.y += w0 * a0.y;
        acc.z += w0 * a1.x; acc.w += w0 * a1.y;
        acc.x += w1 * c0.x; acc.y += w1 * c0.y;
        acc.z += w1 * c1.x; acc.w += w1 * c1.y;
    }
    if (e < end) {
        int2 p = g_csr[e];
        float w = __int_as_float(p.y);
        uint2 v = h2[(size_t)p.x * 32 + lane];
        float2 a0 = __half22float2(*(__half2*)&v.x);
        float2 a1 = __half22float2(*(__half2*)&v.y);
        acc.x += w * a0.x; acc.y += w * a0.y;
        acc.z += w * a1.x; acc.w += w * a1.y;
    }

    acc.x = fmaxf(acc.x, 0.f); acc.y = fmaxf(acc.y, 0.f);
    acc.z = fmaxf(acc.z, 0.f); acc.w = fmaxf(acc.w, 0.f);

    if (!do_dot) {
        __half2 o0 = __float22half2_rn(make_float2(acc.x, acc.y));
        __half2 o1 = __float22half2_rn(make_float2(acc.z, acc.w));
        uint2 o;
        o.x = *(uint32_t*)&o0; o.y = *(uint32_t*)&o1;
        ((uint2*)g_buf)[(size_t)node * 32 + lane] = o;
    } else {
        float4 wf = *(const float4*)&Wf[lane * 4];
        float sum = acc.x * wf.x + acc.y * wf.y + acc.z * wf.z + acc.w * wf.w;
        #pragma unroll
        for (int o = 16; o; o >>= 1) sum += __shfl_xor_sync(0xffffffffu, sum, o);
        if (lane == 0) g_hf[node] = sum;
    }
}

// ------------------------------ final layer --------------------------------
__global__ void k_fin(const float* __restrict__ bf, float* __restrict__ out) {
    int i = blockIdx.x * blockDim.x + threadIdx.x;
    if (i >= NN) return;
    float dv = g_dinv[i];
    float acc = dv * dv * g_hf[i] + bf[0];
    int beg = g_rowptr[i], end = g_rowptr[i + 1];
    for (int e = beg; e < end; e++) {
        int2 p = g_csr[e];
        acc += __int_as_float(p.y) * g_hf[p.x];
    }
    out[i] = acc;
}

// ------------------------------- launch ------------------------------------
extern "C" void kernel_launch(void* const* d_in, const int* in_sizes, int n_in,
                              void* d_out, int out_size) {
    const float* x   = (const float*)d_in[0];
    const int*   ei  = (const int*)d_in[1];
    const float* ew  = (const float*)d_in[2];
    const float* Win = (const float*)d_in[3];
    const float* bin = (const float*)d_in[4];
    const float* Wmd = (const float*)d_in[5];
    const float* bmd = (const float*)d_in[6];
    const float* Wfn = (const float*)d_in[7];
    const float* bfn = (const float*)d_in[8];
    float* out = (float*)d_out;

    static int smem_set = 0;
    if (!smem_set) {
        cudaFuncSetAttribute(k_gemm_tc,
                             cudaFuncAttributeMaxDynamicSharedMemorySize,
                             SMEM_G);
        smem_set = 1;
    }

    __half* x16;
    cudaGetSymbolAddress((void**)&x16, g_x16);
    __half* buf16;
    cudaGetSymbolAddress((void**)&buf16, g_buf);

    const int TB = 256;
    const int gN = (NN + TB - 1) / TB;           // 391
    const int gE = (NE + TB - 1) / TB;           // 6250
    const int gG = (NNP + 127) / 128;            // 782
    const int gA = (NN + 7) / 8;                 // 12500 (warp/node)

    k_deg_init<<<gN, TB>>>();                    // 0
    k_deg_acc<<<gE, TB>>>(ei, ew);               // 1
    k_cvt<<<GX + 128, TB>>>(x, Win, Wmd);        // 2
    k_scan<<<NBLK, 1024>>>();                    // 3
    k_fill<<<gE, TB>>>(ei, ew);                  // 4
    k_gemm_tc<<<gG, TB, SMEM_G>>>(x16, 0);       // 5  <-- profiled

    // layer 1 aggregate (writes relu'd fp16 buf)
    k_gather<<<gA, TB>>>(bin, 0, nullptr);

    // layer 2
    k_gemm_tc<<<gG, TB, SMEM_G>>>(buf16, 1);
    k_gather<<<gA, TB>>>(bmd, 0, nullptr);

    // layer 3 (+ fused final dot)
    k_gemm_tc<<<gG, TB, SMEM_G>>>(buf16, 1);
    k_gather<<<gA, TB>>>(bmd, 1, Wfn);

    // final aggregation (scalar)
    k_fin<<<gN, TB>>>(bfn, out);
}

// round 13
// speedup vs baseline: 2.1715x; 1.0026x over previous
#include <cuda_runtime.h>
#include <cuda_fp16.h>
#include <cstdint>
#include <mma.h>

using namespace nvcuda;

#define NN 100000
#define NNP 100096   // padded to multiple of 128 for unguarded wmma stores
#define NE 1600000
#define F 128
#define NBLK 98      // ceil(NN/1024)
#define GP 136       // GEMM smem pitch (fp16)
#define SMEM_G (3 * 128 * GP * 2)   // 104448 B: A + Whi + Wlo

// -------- scratch (static device globals; no allocations allowed) ----------
__device__ float g_dinv[NN];
__device__ int   g_deg[NN];
__device__ unsigned long long g_desc[NBLK];   // lookback: status<<32 | value
__device__ int   g_rowptr[NN + 1];
__device__ int   g_cursor[NN];
__device__ __align__(16) int2 g_csr[NE];
__device__ __align__(16) __half g_h[(size_t)NNP * F];     // GEMM out (fp16)
__device__ __align__(16) __half g_buf[(size_t)NNP * F];   // relu(agg) (fp16)
__device__ float g_hf[NN];
__device__ __align__(16) __half g_Whi[2][F * F];  // [0]=W_in, [1]=W_mid
__device__ __align__(16) __half g_Wlo[2][F * F];

// ------------------- init + W split (merged prelude) ------------------------
// blocks [0,391): deg/dinv/desc init;  blocks [391,519): W hi/lo split
__global__ void k_pre(const float* __restrict__ Win,
                      const float* __restrict__ Wmd) {
    int bid = blockIdx.x;
    if (bid < 391) {
        int i = bid * 256 + threadIdx.x;
        if (i < NN) { g_dinv[i] = 1.0f; g_deg[i] = 0; }
        if (i < NBLK) g_desc[i] = 0ull;
    } else {
        int r = bid - 391;                        // 0..127
        int which = r >> 6;                       // 0=W_in, 1=W_mid
        int i = (r & 63) * 256 + threadIdx.x;     // 0..16383
        const float* W = which ? Wmd : Win;
        float w = W[i];
        __half h = __float2half(w);
        g_Whi[which][i] = h;
        g_Wlo[which][i] = __float2half(w - __half2float(h));
    }
}

__global__ void k_deg_acc(const int* __restrict__ ei,
                          const float* __restrict__ ew) {
    int e = blockIdx.x * blockDim.x + threadIdx.x;
    if (e < NE) {
        int d = ei[NE + e];
        atomicAdd(&g_dinv[d], ew[e]);
        atomicAdd(&g_deg[d], 1);
    }
}

// ------------- single-pass exclusive scan (decoupled lookback) --------------
// grid = NBLK (98) blocks, all co-resident on 148 SMs -> spin is safe.
__global__ __launch_bounds__(1024) void k_scan() {
    __shared__ int warps[32];
    __shared__ int sprefix;
    int t = threadIdx.x, b = blockIdx.x, i = b * 1024 + t;
    if (i < NN) g_dinv[i] = rsqrtf(g_dinv[i]);   // deg >= 1 always
    int v = (i < NN) ? g_deg[i] : 0;
    int lane = t & 31, w = t >> 5;

    // warp-level inclusive scan
    int s = v;
    #pragma unroll
    for (int o = 1; o < 32; o <<= 1) {
        int u = __shfl_up_sync(0xffffffffu, s, o);
        if (lane >= o) s += u;
    }
    if (lane == 31) warps[w] = s;
    __syncthreads();

    if (w == 0) {
        int ws = warps[lane];
        int ss = ws;
        #pragma unroll
        for (int o = 1; o < 32; o <<= 1) {
            int u = __shfl_up_sync(0xffffffffu, ss, o);
            if (lane >= o) ss += u;
        }
        warps[lane] = ss - ws;                    // exclusive warp offsets
        if (lane == 31) {
            unsigned agg = (unsigned)ss;          // block total
            atomicExch(&g_desc[b], (1ull << 32) | agg);
            unsigned sum = 0;
            for (int j = b - 1; j >= 0;) {
                unsigned long long d = atomicAdd(&g_desc[j], 0ull);
                unsigned st = (unsigned)(d >> 32);
                if (st == 0) continue;            // not yet published
                sum += (unsigned)d;
                if (st == 2) break;               // inclusive prefix
                j--;                              // aggregate: keep walking
            }
            atomicExch(&g_desc[b], (2ull << 32) | (sum + agg));
            sprefix = (int)sum;
            if (b == NBLK - 1) g_rowptr[NN] = (int)(sum + agg);
        }
    }
    __syncthreads();
    if (i < NN) {
        int ex = s - v + warps[w] + sprefix;
        g_rowptr[i] = ex;
        g_cursor[i] = ex;
    }
}

__global__ void k_fill(const int* __restrict__ ei,
                       const float* __restrict__ ew) {
    int e = blockIdx.x * blockDim.x + threadIdx.x;
    if (e >= NE) return;
    int s = ei[e], d = ei[NE + e];
    int pos = atomicAdd(&g_cursor[d], 1);
    float w = g_dinv[s] * ew[e] * g_dinv[d];
    g_csr[pos] = make_int2(s, __float_as_int(w));
}

// ------------- tensor-core GEMM: fp16 A x (fp16 hi+lo) W -------------------
// Full A tile (128x128) + full W images resident in smem; single sync.
// fp32_in: A is fp32 (layer 1 reads x directly, converts in prologue).
__global__ __launch_bounds__(256) void k_gemm_tc(const void* __restrict__ Ap,
                                                 int widx, int fp32_in) {
    extern __shared__ __half sm[];
    __half* Ah = sm;                    // 128 x GP
    __half* Wh = sm + 128 * GP;
    __half* Wl = Wh + 128 * GP;
    int tid = threadIdx.x;
    int wid = tid >> 5;
    int row0 = blockIdx.x * 128;
    const __half* __restrict__ Whig = g_Whi[widx];
    const __half* __restrict__ Wlog = g_Wlo[widx];

    // A: 2048 8-half groups (8/thread)
    if (fp32_in) {
        const float* __restrict__ A = (const float*)Ap;
        #pragma unroll
        for (int i = 0; i < 8; i++) {
            int idx = tid + i * 256;
            int r = idx >> 4, q = idx & 15;
            int row = row0 + r;
            uint4 o = make_uint4(0u, 0u, 0u, 0u);
            if (row < NN) {
                float4 a = *(const float4*)&A[(size_t)row * F + q * 8];
                float4 b = *(const float4*)&A[(size_t)row * F + q * 8 + 4];
                __half2 h0 = __float22half2_rn(make_float2(a.x, a.y));
                __half2 h1 = __float22half2_rn(make_float2(a.z, a.w));
                __half2 h2 = __float22half2_rn(make_float2(b.x, b.y));
                __half2 h3 = __float22half2_rn(make_float2(b.z, b.w));
                o.x = *(uint32_t*)&h0; o.y = *(uint32_t*)&h1;
                o.z = *(uint32_t*)&h2; o.w = *(uint32_t*)&h3;
            }
            *(uint4*)&Ah[r * GP + q * 8] = o;
        }
    } else {
        const __half* __restrict__ A = (const __half*)Ap;
        #pragma unroll
        for (int i = 0; i < 8; i++) {
            int idx = tid + i * 256;
            int r = idx >> 4, q = idx & 15;
            int row = row0 + r;
            uint4 v = make_uint4(0u, 0u, 0u, 0u);
            if (row < NN) v = *(const uint4*)&A[(size_t)row * F + q * 8];
            *(uint4*)&Ah[r * GP + q * 8] = v;
        }
    }
    // W: 2048 uint4 per image (8/thread each)
    #pragma unroll
    for (int i = 0; i < 8; i++) {
        int idx = tid + i * 256;
        int k = idx >> 4, q = idx & 15;
        *(uint4*)&Wh[k * GP + q * 8] = *(const uint4*)&Whig[k * F + q * 8];
        *(uint4*)&Wl[k * GP + q * 8] = *(const uint4*)&Wlog[k * F + q * 8];
    }
    __syncthreads();

    wmma::fragment<wmma::accumulator, 16, 16, 16, float> acc[8];
    #pragma unroll
    for (int c = 0; c < 8; c++) wmma::fill_fragment(acc[c], 0.0f);

    #pragma unroll
    for (int ks = 0; ks < 8; ks++) {
        wmma::fragment<wmma::matrix_a, 16, 16, 16, __half, wmma::row_major> a;
        wmma::load_matrix_sync(a, &Ah[(wid * 16) * GP + ks * 16], GP);
        #pragma unroll
        for (int c = 0; c < 8; c++) {
            wmma::fragment<wmma::matrix_b, 16, 16, 16, __half,
                           wmma::row_major> bh, bl;
            wmma::load_matrix_sync(bh, &Wh[(ks * 16) * GP + c * 16], GP);
            wmma::load_matrix_sync(bl, &Wl[(ks * 16) * GP + c * 16], GP);
            wmma::mma_sync(acc[c], a, bh, acc[c]);
            wmma::mma_sync(acc[c], a, bl, acc[c]);
        }
    }
    // store 16x128 per warp as fp16 (f32/f16 acc fragments share layout)
    __half* outp = &g_h[(size_t)(row0 + wid * 16) * F];
    #pragma unroll
    for (int c = 0; c < 8; c++) {
        wmma::fragment<wmma::accumulator, 16, 16, 16, __half> hacc;
        #pragma unroll
        for (int i = 0; i < 8; i++) hacc.x[i] = __float2half(acc[c].x[i]);
        wmma::store_matrix_sync(outp + c * 16, hacc, F, wmma::mem_row_major);
    }
}

// ----------------------- aggregation: CSR gather ----------------------------
#define EDGE_FMA(p_src, p_w)                                                 \
    do {                                                                     \
        float _w = __int_as_float(p_w);                                      \
        uint2 _v = h2[(size_t)(p_src) * 32 + lane];                          \
        float2 _a0 = __half22float2(*(__half2*)&_v.x);                       \
        float2 _a1 = __half22float2(*(__half2*)&_v.y);                       \
        acc.x += _w * _a0.x; acc.y += _w * _a0.y;                            \
        acc.z += _w * _a1.x; acc.w += _w * _a1.y;                            \
    } while (0)

__global__ __launch_bounds__(256) void k_gather(const float* __restrict__ b,
                                                int do_dot,
                                                const float* __restrict__ Wf) {
    int node = blockIdx.x * 8 + (threadIdx.x >> 5);
    int lane = threadIdx.x & 31;
    if (node >= NN) return;
    const uint2* __restrict__ h2 = (const uint2*)g_h;

    float dv = g_dinv[node];
    float s2 = dv * dv;
    uint2 hv = h2[(size_t)node * 32 + lane];
    float2 f0 = __half22float2(*(__half2*)&hv.x);
    float2 f1 = __half22float2(*(__half2*)&hv.y);
    float4 bv = *(const float4*)&b[lane * 4];
    float4 acc;
    acc.x = s2 * f0.x + bv.x; acc.y = s2 * f0.y + bv.y;
    acc.z = s2 * f1.x + bv.z; acc.w = s2 * f1.y + bv.w;

    int beg = g_rowptr[node], end = g_rowptr[node + 1];
    int e = beg;
    if ((e & 1) && e < end) {                    // peel to 16B alignment
        int2 p = g_csr[e];
        EDGE_FMA(p.x, p.y);
        e++;
    }
    // 4-edge unroll: 4 independent row loads in flight
    for (; e + 4 <= end; e += 4) {
        int4 p0 = *(const int4*)&g_csr[e];
        int4 p1 = *(const int4*)&g_csr[e + 2];
        float w0 = __int_as_float(p0.y), w1 = __int_as_float(p0.w);
        float w2 = __int_as_float(p1.y), w3 = __int_as_float(p1.w);
        uint2 v0 = h2[(size_t)p0.x * 32 + lane];
        uint2 v1 = h2[(size_t)p0.z * 32 + lane];
        uint2 v2 = h2[(size_t)p1.x * 32 + lane];
        uint2 v3 = h2[(size_t)p1.z * 32 + lane];
        float2 a0 = __half22float2(*(__half2*)&v0.x);
        float2 a1 = __half22float2(*(__half2*)&v0.y);
        acc.x += w0 * a0.x; acc.y += w0 * a0.y;
        acc.z += w0 * a1.x; acc.w += w0 * a1.y;
        a0 = __half22float2(*(__half2*)&v1.x);
        a1 = __half22float2(*(__half2*)&v1.y);
        acc.x += w1 * a0.x; acc.y += w1 * a0.y;
        acc.z += w1 * a1.x; acc.w += w1 * a1.y;
        a0 = __half22float2(*(__half2*)&v2.x);
        a1 = __half22float2(*(__half2*)&v2.y);
        acc.x += w2 * a0.x; acc.y += w2 * a0.y;
        acc.z += w2 * a1.x; acc.w += w2 * a1.y;
        a0 = __half22float2(*(__half2*)&v3.x);
        a1 = __half22float2(*(__half2*)&v3.y);
        acc.x += w3 * a0.x; acc.y += w3 * a0.y;
        acc.z += w3 * a1.x; acc.w += w3 * a1.y;
    }
    if (e + 2 <= end) {
        int4 p = *(const int4*)&g_csr[e];
        float w0 = __int_as_float(p.y), w1 = __int_as_float(p.w);
        uint2 v0 = h2[(size_t)p.x * 32 + lane];
        uint2 v1 = h2[(size_t)p.z * 32 + lane];
        float2 a0 = __half22float2(*(__half2*)&v0.x);
        float2 a1 = __half22float2(*(__half2*)&v0.y);
        acc.x += w0 * a0.x; acc.y += w0 * a0.y;
        acc.z += w0 * a1.x; acc.w += w0 * a1.y;
        a0 = __half22float2(*(__half2*)&v1.x);
        a1 = __half22float2(*(__half2*)&v1.y);
        acc.x += w1 * a0.x; acc.y += w1 * a0.y;
        acc.z += w1 * a1.x; acc.w += w1 * a1.y;
        e += 2;
    }
    if (e < end) {
        int2 p = g_csr[e];
        EDGE_FMA(p.x, p.y);
    }

    acc.x = fmaxf(acc.x, 0.f); acc.y = fmaxf(acc.y, 0.f);
    acc.z = fmaxf(acc.z, 0.f); acc.w = fmaxf(acc.w, 0.f);

    if (!do_dot) {
        __half2 o0 = __float22half2_rn(make_float2(acc.x, acc.y));
        __half2 o1 = __float22half2_rn(make_float2(acc.z, acc.w));
        uint2 o;
        o.x = *(uint32_t*)&o0; o.y = *(uint32_t*)&o1;
        ((uint2*)g_buf)[(size_t)node * 32 + lane] = o;
    } else {
        float4 wf = *(const float4*)&Wf[lane * 4];
        float sum = acc.x * wf.x + acc.y * wf.y + acc.z * wf.z + acc.w * wf.w;
        #pragma unroll
        for (int o = 16; o; o >>= 1) sum += __shfl_xor_sync(0xffffffffu, sum, o);
        if (lane == 0) g_hf[node] = sum;
    }
}

// ------------------------------ final layer --------------------------------
__global__ void k_fin(const float* __restrict__ bf, float* __restrict__ out) {
    int i = blockIdx.x * blockDim.x + threadIdx.x;
    if (i >= NN) return;
    float dv = g_dinv[i];
    float acc = dv * dv * g_hf[i] + bf[0];
    int beg = g_rowptr[i], end = g_rowptr[i + 1];
    for (int e = beg; e < end; e++) {
        int2 p = g_csr[e];
        acc += __int_as_float(p.y) * g_hf[p.x];
    }
    out[i] = acc;
}

// ------------------------------- launch ------------------------------------
extern "C" void kernel_launch(void* const* d_in, const int* in_sizes, int n_in,
                              void* d_out, int out_size) {
    const float* x   = (const float*)d_in[0];
    const int*   ei  = (const int*)d_in[1];
    const float* ew  = (const float*)d_in[2];
    const float* Win = (const float*)d_in[3];
    const float* bin = (const float*)d_in[4];
    const float* Wmd = (const float*)d_in[5];
    const float* bmd = (const float*)d_in[6];
    const float* Wfn = (const float*)d_in[7];
    const float* bfn = (const float*)d_in[8];
    float* out = (float*)d_out;

    static int smem_set = 0;
    if (!smem_set) {
        cudaFuncSetAttribute(k_gemm_tc,
                             cudaFuncAttributeMaxDynamicSharedMemorySize,
                             SMEM_G);
        smem_set = 1;
    }

    __half* buf16;
    cudaGetSymbolAddress((void**)&buf16, g_buf);

    const int TB = 256;
    const int gN = (NN + TB - 1) / TB;           // 391
    const int gE = (NE + TB - 1) / TB;           // 6250
    const int gG = (NNP + 127) / 128;            // 782
    const int gA = (NN + 7) / 8;                 // 12500 (warp/node)

    k_pre<<<gN + 128, TB>>>(Win, Wmd);           // 0
    k_deg_acc<<<gE, TB>>>(ei, ew);               // 1
    k_scan<<<NBLK, 1024>>>();                    // 2
    k_fill<<<gE, TB>>>(ei, ew);                  // 3
    k_gemm_tc<<<gG, TB, SMEM_G>>>(x, 0, 1);      // 4 (fp32 x in)

    // layer 1 aggregate (writes relu'd fp16 buf)
    k_gather<<<gA, TB>>>(bin, 0, nullptr);       // 5

    // layer 2
    k_gemm_tc<<<gG, TB, SMEM_G>>>(buf16, 1, 0);  // 6
    k_gather<<<gA, TB>>>(bmd, 0, nullptr);       // 7

    // layer 3 (+ fused final dot)
    k_gemm_tc<<<gG, TB, SMEM_G>>>(buf16, 1, 0);  // 8
    k_gather<<<gA, TB>>>(bmd, 1, Wfn);           // 9

    // final aggregation (scalar)
    k_fin<<<gN, TB>>>(bfn, out);                 // 10
}

// round 14
// speedup vs baseline: 2.2487x; 1.0355x over previous
#include <cuda_runtime.h>
#include <cuda_fp16.h>
#include <cstdint>
#include <mma.h>

using namespace nvcuda;

#define NN 100000
#define NNP 100096   // padded to multiple of 128 for unguarded wmma stores
#define NE 1600000
#define F 128
#define NBLK 98      // ceil(NN/1024)
#define GP 136       // GEMM smem pitch (fp16)
#define SMEM_G (3 * 128 * GP * 2)   // 104448 B: A + Whi + Wlo

// -------- scratch (static device globals; no allocations allowed) ----------
__device__ float g_dinv[NN];
__device__ int   g_deg[NN];
__device__ unsigned long long g_desc[NBLK];   // lookback: status<<32 | value
__device__ int   g_rowptr[NN + 1];
__device__ int   g_eli[NE];                   // edge's index within dst row
__device__ __align__(16) int2 g_csr[NE];
__device__ __align__(16) __half g_h[(size_t)NNP * F];     // GEMM out (fp16)
__device__ __align__(16) __half g_buf[(size_t)NNP * F];   // relu(agg) (fp16)
__device__ float g_hf[NN];
__device__ __align__(16) __half g_Whi[2][F * F];  // [0]=W_in, [1]=W_mid
__device__ __align__(16) __half g_Wlo[2][F * F];

// ------------------- init + W split (merged prelude) ------------------------
// blocks [0,391): deg/dinv/desc init;  blocks [391,519): W hi/lo split
__global__ void k_pre(const float* __restrict__ Win,
                      const float* __restrict__ Wmd) {
    int bid = blockIdx.x;
    if (bid < 391) {
        int i = bid * 256 + threadIdx.x;
        if (i < NN) { g_dinv[i] = 1.0f; g_deg[i] = 0; }
        if (i < NBLK) g_desc[i] = 0ull;
    } else {
        int r = bid - 391;                        // 0..127
        int which = r >> 6;                       // 0=W_in, 1=W_mid
        int i = (r & 63) * 256 + threadIdx.x;     // 0..16383
        const float* W = which ? Wmd : Win;
        float w = W[i];
        __half h = __float2half(w);
        g_Whi[which][i] = h;
        g_Wlo[which][i] = __float2half(w - __half2float(h));
    }
}

// degree accumulation; the int atomic's return value IS the edge's slot
__global__ void k_deg_acc(const int* __restrict__ ei,
                          const float* __restrict__ ew) {
    int e = blockIdx.x * blockDim.x + threadIdx.x;
    if (e < NE) {
        int d = ei[NE + e];
        atomicAdd(&g_dinv[d], ew[e]);
        g_eli[e] = atomicAdd(&g_deg[d], 1);
    }
}

// ------------- single-pass exclusive scan (decoupled lookback) --------------
__global__ __launch_bounds__(1024) void k_scan() {
    __shared__ int warps[32];
    __shared__ int sprefix;
    int t = threadIdx.x, b = blockIdx.x, i = b * 1024 + t;
    if (i < NN) g_dinv[i] = rsqrtf(g_dinv[i]);   // deg >= 1 always
    int v = (i < NN) ? g_deg[i] : 0;
    int lane = t & 31, w = t >> 5;

    int s = v;
    #pragma unroll
    for (int o = 1; o < 32; o <<= 1) {
        int u = __shfl_up_sync(0xffffffffu, s, o);
        if (lane >= o) s += u;
    }
    if (lane == 31) warps[w] = s;
    __syncthreads();

    if (w == 0) {
        int ws = warps[lane];
        int ss = ws;
        #pragma unroll
        for (int o = 1; o < 32; o <<= 1) {
            int u = __shfl_up_sync(0xffffffffu, ss, o);
            if (lane >= o) ss += u;
        }
        warps[lane] = ss - ws;                    // exclusive warp offsets
        if (lane == 31) {
            unsigned agg = (unsigned)ss;          // block total
            atomicExch(&g_desc[b], (1ull << 32) | agg);
            unsigned sum = 0;
            for (int j = b - 1; j >= 0;) {
                unsigned long long d = atomicAdd(&g_desc[j], 0ull);
                unsigned st = (unsigned)(d >> 32);
                if (st == 0) continue;            // not yet published
                sum += (unsigned)d;
                if (st == 2) break;               // inclusive prefix
                j--;                              // aggregate: keep walking
            }
            atomicExch(&g_desc[b], (2ull << 32) | (sum + agg));
            sprefix = (int)sum;
            if (b == NBLK - 1) g_rowptr[NN] = (int)(sum + agg);
        }
    }
    __syncthreads();
    if (i < NN) g_rowptr[i] = s - v + warps[w] + sprefix;
}

// atomic-free CSR fill: pos = rowptr[dst] + per-edge slot from deg_acc
__global__ void k_fill(const int* __restrict__ ei,
                       const float* __restrict__ ew) {
    int e = blockIdx.x * blockDim.x + threadIdx.x;
    if (e >= NE) return;
    int s = ei[e], d = ei[NE + e];
    int pos = g_rowptr[d] + g_eli[e];
    float w = g_dinv[s] * ew[e] * g_dinv[d];
    g_csr[pos] = make_int2(s, __float_as_int(w));
}

// ------------- tensor-core GEMM: fp16 A x (fp16 hi+lo) W -------------------
__global__ __launch_bounds__(256) void k_gemm_tc(const void* __restrict__ Ap,
                                                 int widx, int fp32_in) {
    extern __shared__ __half sm[];
    __half* Ah = sm;                    // 128 x GP
    __half* Wh = sm + 128 * GP;
    __half* Wl = Wh + 128 * GP;
    int tid = threadIdx.x;
    int wid = tid >> 5;
    int row0 = blockIdx.x * 128;
    const __half* __restrict__ Whig = g_Whi[widx];
    const __half* __restrict__ Wlog = g_Wlo[widx];

    if (fp32_in) {
        const float* __restrict__ A = (const float*)Ap;
        #pragma unroll
        for (int i = 0; i < 8; i++) {
            int idx = tid + i * 256;
            int r = idx >> 4, q = idx & 15;
            int row = row0 + r;
            uint4 o = make_uint4(0u, 0u, 0u, 0u);
            if (row < NN) {
                float4 a = *(const float4*)&A[(size_t)row * F + q * 8];
                float4 b = *(const float4*)&A[(size_t)row * F + q * 8 + 4];
                __half2 h0 = __float22half2_rn(make_float2(a.x, a.y));
                __half2 h1 = __float22half2_rn(make_float2(a.z, a.w));
                __half2 h2 = __float22half2_rn(make_float2(b.x, b.y));
                __half2 h3 = __float22half2_rn(make_float2(b.z, b.w));
                o.x = *(uint32_t*)&h0; o.y = *(uint32_t*)&h1;
                o.z = *(uint32_t*)&h2; o.w = *(uint32_t*)&h3;
            }
            *(uint4*)&Ah[r * GP + q * 8] = o;
        }
    } else {
        const __half* __restrict__ A = (const __half*)Ap;
        #pragma unroll
        for (int i = 0; i < 8; i++) {
            int idx = tid + i * 256;
            int r = idx >> 4, q = idx & 15;
            int row = row0 + r;
            uint4 v = make_uint4(0u, 0u, 0u, 0u);
            if (row < NN) v = *(const uint4*)&A[(size_t)row * F + q * 8];
            *(uint4*)&Ah[r * GP + q * 8] = v;
        }
    }
    #pragma unroll
    for (int i = 0; i < 8; i++) {
        int idx = tid + i * 256;
        int k = idx >> 4, q = idx & 15;
        *(uint4*)&Wh[k * GP + q * 8] = *(const uint4*)&Whig[k * F + q * 8];
        *(uint4*)&Wl[k * GP + q * 8] = *(const uint4*)&Wlog[k * F + q * 8];
    }
    __syncthreads();

    wmma::fragment<wmma::accumulator, 16, 16, 16, float> acc[8];
    #pragma unroll
    for (int c = 0; c < 8; c++) wmma::fill_fragment(acc[c], 0.0f);

    #pragma unroll
    for (int ks = 0; ks < 8; ks++) {
        wmma::fragment<wmma::matrix_a, 16, 16, 16, __half, wmma::row_major> a;
        wmma::load_matrix_sync(a, &Ah[(wid * 16) * GP + ks * 16], GP);
        #pragma unroll
        for (int c = 0; c < 8; c++) {
            wmma::fragment<wmma::matrix_b, 16, 16, 16, __half,
                           wmma::row_major> bh, bl;
            wmma::load_matrix_sync(bh, &Wh[(ks * 16) * GP + c * 16], GP);
            wmma::load_matrix_sync(bl, &Wl[(ks * 16) * GP + c * 16], GP);
            wmma::mma_sync(acc[c], a, bh, acc[c]);
            wmma::mma_sync(acc[c], a, bl, acc[c]);
        }
    }
    __half* outp = &g_h[(size_t)(row0 + wid * 16) * F];
    #pragma unroll
    for (int c = 0; c < 8; c++) {
        wmma::fragment<wmma::accumulator, 16, 16, 16, __half> hacc;
        #pragma unroll
        for (int i = 0; i < 8; i++) hacc.x[i] = __float2half(acc[c].x[i]);
        wmma::store_matrix_sync(outp + c * 16, hacc, F, wmma::mem_row_major);
    }
}

// ----------------------- aggregation: CSR gather ----------------------------
#define EDGE_FMA(p_src, p_w)                                                 \
    do {                                                                     \
        float _w = __int_as_float(p_w);                                      \
        uint2 _v = h2[(size_t)(p_src) * 32 + lane];                          \
        float2 _a0 = __half22float2(*(__half2*)&_v.x);                       \
        float2 _a1 = __half22float2(*(__half2*)&_v.y);                       \
        acc.x += _w * _a0.x; acc.y += _w * _a0.y;                            \
        acc.z += _w * _a1.x; acc.w += _w * _a1.y;                            \
    } while (0)

__global__ __launch_bounds__(256) void k_gather(const float* __restrict__ b,
                                                int do_dot,
                                                const float* __restrict__ Wf) {
    int node = blockIdx.x * 8 + (threadIdx.x >> 5);
    int lane = threadIdx.x & 31;
    if (node >= NN) return;
    const uint2* __restrict__ h2 = (const uint2*)g_h;

    float dv = g_dinv[node];
    float s2 = dv * dv;
    uint2 hv = h2[(size_t)node * 32 + lane];
    float2 f0 = __half22float2(*(__half2*)&hv.x);
    float2 f1 = __half22float2(*(__half2*)&hv.y);
    float4 bv = *(const float4*)&b[lane * 4];
    float4 acc;
    acc.x = s2 * f0.x + bv.x; acc.y = s2 * f0.y + bv.y;
    acc.z = s2 * f1.x + bv.z; acc.w = s2 * f1.y + bv.w;

    int beg = g_rowptr[node], end = g_rowptr[node + 1];
    int e = beg;
    if ((e & 1) && e < end) {                    // peel to 16B alignment
        int2 p = g_csr[e];
        EDGE_FMA(p.x, p.y);
        e++;
    }
    for (; e + 4 <= end; e += 4) {
        int4 p0 = *(const int4*)&g_csr[e];
        int4 p1 = *(const int4*)&g_csr[e + 2];
        float w0 = __int_as_float(p0.y), w1 = __int_as_float(p0.w);
        float w2 = __int_as_float(p1.y), w3 = __int_as_float(p1.w);
        uint2 v0 = h2[(size_t)p0.x * 32 + lane];
        uint2 v1 = h2[(size_t)p0.z * 32 + lane];
        uint2 v2 = h2[(size_t)p1.x * 32 + lane];
        uint2 v3 = h2[(size_t)p1.z * 32 + lane];
        float2 a0 = __half22float2(*(__half2*)&v0.x);
        float2 a1 = __half22float2(*(__half2*)&v0.y);
        acc.x += w0 * a0.x; acc.y += w0 * a0.y;
        acc.z += w0 * a1.x; acc.w += w0 * a1.y;
        a0 = __half22float2(*(__half2*)&v1.x);
        a1 = __half22float2(*(__half2*)&v1.y);
        acc.x += w1 * a0.x; acc.y += w1 * a0.y;
        acc.z += w1 * a1.x; acc.w += w1 * a1.y;
        a0 = __half22float2(*(__half2*)&v2.x);
        a1 = __half22float2(*(__half2*)&v2.y);
        acc.x += w2 * a0.x; acc.y += w2 * a0.y;
        acc.z += w2 * a1.x; acc.w += w2 * a1.y;
        a0 = __half22float2(*(__half2*)&v3.x);
        a1 = __half22float2(*(__half2*)&v3.y);
        acc.x += w3 * a0.x; acc.y += w3 * a0.y;
        acc.z += w3 * a1.x; acc.w += w3 * a1.y;
    }
    if (e + 2 <= end) {
        int4 p = *(const int4*)&g_csr[e];
        float w0 = __int_as_float(p.y), w1 = __int_as_float(p.w);
        uint2 v0 = h2[(size_t)p.x * 32 + lane];
        uint2 v1 = h2[(size_t)p.z * 32 + lane];
        float2 a0 = __half22float2(*(__half2*)&v0.x);
        float2 a1 = __half22float2(*(__half2*)&v0.y);
        acc.x += w0 * a0.x; acc.y += w0 * a0.y;
        acc.z += w0 * a1.x; acc.w += w0 * a1.y;
        a0 = __half22float2(*(__half2*)&v1.x);
        a1 = __half22float2(*(__half2*)&v1.y);
        acc.x += w1 * a0.x; acc.y += w1 * a0.y;
        acc.z += w1 * a1.x; acc.w += w1 * a1.y;
        e += 2;
    }
    if (e < end) {
        int2 p = g_csr[e];
        EDGE_FMA(p.x, p.y);
    }

    acc.x = fmaxf(acc.x, 0.f); acc.y = fmaxf(acc.y, 0.f);
    acc.z = fmaxf(acc.z, 0.f); acc.w = fmaxf(acc.w, 0.f);

    if (!do_dot) {
        __half2 o0 = __float22half2_rn(make_float2(acc.x, acc.y));
        __half2 o1 = __float22half2_rn(make_float2(acc.z, acc.w));
        uint2 o;
        o.x = *(uint32_t*)&o0; o.y = *(uint32_t*)&o1;
        ((uint2*)g_buf)[(size_t)node * 32 + lane] = o;
    } else {
        float4 wf = *(const float4*)&Wf[lane * 4];
        float sum = acc.x * wf.x + acc.y * wf.y + acc.z * wf.z + acc.w * wf.w;
        #pragma unroll
        for (int o = 16; o; o >>= 1) sum += __shfl_xor_sync(0xffffffffu, sum, o);
        if (lane == 0) g_hf[node] = sum;
    }
}

// ------------------------------ final layer --------------------------------
__global__ void k_fin(const float* __restrict__ bf, float* __restrict__ out) {
    int i = blockIdx.x * blockDim.x + threadIdx.x;
    if (i >= NN) return;
    float dv = g_dinv[i];
    float acc = dv * dv * g_hf[i] + bf[0];
    int beg = g_rowptr[i], end = g_rowptr[i + 1];
    for (int e = beg; e < end; e++) {
        int2 p = g_csr[e];
        acc += __int_as_float(p.y) * g_hf[p.x];
    }
    out[i] = acc;
}

// ------------------------------- launch ------------------------------------
extern "C" void kernel_launch(void* const* d_in, const int* in_sizes, int n_in,
                              void* d_out, int out_size) {
    const float* x   = (const float*)d_in[0];
    const int*   ei  = (const int*)d_in[1];
    const float* ew  = (const float*)d_in[2];
    const float* Win = (const float*)d_in[3];
    const float* bin = (const float*)d_in[4];
    const float* Wmd = (const float*)d_in[5];
    const float* bmd = (const float*)d_in[6];
    const float* Wfn = (const float*)d_in[7];
    const float* bfn = (const float*)d_in[8];
    float* out = (float*)d_out;

    static cudaStream_t sA = nullptr;
    static cudaEvent_t evFork = nullptr, evJoin = nullptr;
    if (!sA) {
        cudaFuncSetAttribute(k_gemm_tc,
                             cudaFuncAttributeMaxDynamicSharedMemorySize,
                             SMEM_G);
        cudaStreamCreateWithFlags(&sA, cudaStreamNonBlocking);
        cudaEventCreateWithFlags(&evFork, cudaEventDisableTiming);
        cudaEventCreateWithFlags(&evJoin, cudaEventDisableTiming);
    }

    __half* buf16;
    cudaGetSymbolAddress((void**)&buf16, g_buf);

    const int TB = 256;
    const int gN = (NN + TB - 1) / TB;           // 391
    const int gE = (NE + TB - 1) / TB;           // 6250
    const int gG = (NNP + 127) / 128;            // 782
    const int gA = (NN + 7) / 8;                 // 12500 (warp/node)

    // prelude on main stream (init + W split)
    k_pre<<<gN + 128, TB>>>(Win, Wmd);
    cudaEventRecord(evFork, 0);

    // CSR-build chain on side stream, overlapped with GEMM-1 on main stream
    cudaStreamWaitEvent(sA, evFork, 0);
    k_deg_acc<<<gE, TB, 0, sA>>>(ei, ew);
    k_scan<<<NBLK, 1024, 0, sA>>>();
    k_fill<<<gE, TB, 0, sA>>>(ei, ew);
    cudaEventRecord(evJoin, sA);

    k_gemm_tc<<<gG, TB, SMEM_G>>>(x, 0, 1);      // fp32 x in, parallel w/ chain
    cudaStreamWaitEvent(0, evJoin, 0);

    // layer 1 aggregate (needs fill + gemm1)
    k_gather<<<gA, TB>>>(bin, 0, nullptr);

    // layer 2
    k_gemm_tc<<<gG, TB, SMEM_G>>>(buf16, 1, 0);
    k_gather<<<gA, TB>>>(bmd, 0, nullptr);

    // layer 3 (+ fused final dot)
    k_gemm_tc<<<gG, TB, SMEM_G>>>(buf16, 1, 0);
    k_gather<<<gA, TB>>>(bmd, 1, Wfn);

    // final aggregation (scalar)
    k_fin<<<gN, TB>>>(bfn, out);
}

// round 16
// speedup vs baseline: 2.4733x; 1.0999x over previous
#include <cuda_runtime.h>
#include <cuda_fp16.h>
#include <cstdint>
#include <mma.h>

using namespace nvcuda;

#define NN 100000
#define NNP 100096   // padded to multiple of 128 for unguarded wmma stores
#define NE 1600000
#define F 128
#define NBLK 98      // ceil(NN/1024)
#define GP 136       // GEMM smem pitch (fp16)
#define SMEM_G (3 * 128 * GP * 2)   // 104448 B: A + Whi + Wlo
#define WSCALE 16777216.0f          // 2^24 fixed-point for edge weights

// -------- scratch (static device globals; no allocations allowed) ----------
__device__ float g_dinv[NN];
__device__ unsigned long long g_cnt[NN];      // count<<40 | wsum*2^24
__device__ unsigned long long g_desc[NBLK];   // lookback: status<<32 | value
__device__ int   g_rowptr[NN + 1];
__device__ int   g_eli[NE];                   // edge's index within dst row
__device__ __align__(16) int2 g_csr[NE];
__device__ __align__(16) __half g_h[(size_t)NNP * F];     // GEMM out (fp16)
__device__ __align__(16) __half g_buf[(size_t)NNP * F];   // relu(agg) (fp16)
__device__ float g_hf[NN];
__device__ __align__(16) __half g_Whi[2][F * F];  // [0]=W_in, [1]=W_mid
__device__ __align__(16) __half g_Wlo[2][F * F];

// ------------------- init + W split (merged prelude) ------------------------
__global__ void k_pre(const float* __restrict__ Win,
                      const float* __restrict__ Wmd) {
    int bid = blockIdx.x;
    if (bid < 391) {
        int i = bid * 256 + threadIdx.x;
        if (i < NN) g_cnt[i] = 0ull;
        if (i < NBLK) g_desc[i] = 0ull;
    } else {
        int r = bid - 391;                        // 0..127
        int which = r >> 6;                       // 0=W_in, 1=W_mid
        int i = (r & 63) * 256 + threadIdx.x;     // 0..16383
        const float* W = which ? Wmd : Win;
        float w = W[i];
        __half h = __float2half(w);
        g_Whi[which][i] = h;
        g_Wlo[which][i] = __float2half(w - __half2float(h));
    }
}

// one packed 64-bit atomic: bits[40,64)=count, bits[0,40)=wsum fixed-point
__global__ void k_deg_acc(const int* __restrict__ ei,
                          const float* __restrict__ ew) {
    int e = blockIdx.x * blockDim.x + threadIdx.x;
    if (e < NE) {
        int d = ei[NE + e];
        unsigned long long inc =
            (1ull << 40) | (unsigned long long)__float2uint_rn(ew[e] * WSCALE);
        unsigned long long old = atomicAdd(&g_cnt[d], inc);
        g_eli[e] = (int)(old >> 40);
    }
}

// ------------- single-pass exclusive scan (decoupled lookback) --------------
__global__ __launch_bounds__(1024) void k_scan() {
    __shared__ int warps[32];
    __shared__ int sprefix;
    int t = threadIdx.x, b = blockIdx.x, i = b * 1024 + t;
    int v = 0;
    if (i < NN) {
        unsigned long long pk = g_cnt[i];
        v = (int)(pk >> 40);
        float wsum = (float)(pk & ((1ull << 40) - 1)) * (1.0f / WSCALE);
        g_dinv[i] = rsqrtf(1.0f + wsum);          // deg >= 1 always
    }
    int lane = t & 31, w = t >> 5;

    int s = v;
    #pragma unroll
    for (int o = 1; o < 32; o <<= 1) {
        int u = __shfl_up_sync(0xffffffffu, s, o);
        if (lane >= o) s += u;
    }
    if (lane == 31) warps[w] = s;
    __syncthreads();

    if (w == 0) {
        int ws = warps[lane];
        int ss = ws;
        #pragma unroll
        for (int o = 1; o < 32; o <<= 1) {
            int u = __shfl_up_sync(0xffffffffu, ss, o);
            if (lane >= o) ss += u;
        }
        warps[lane] = ss - ws;                    // exclusive warp offsets
        if (lane == 31) {
            unsigned agg = (unsigned)ss;          // block total
            atomicExch(&g_desc[b], (1ull << 32) | agg);
            unsigned sum = 0;
            for (int j = b - 1; j >= 0;) {
                unsigned long long d = atomicAdd(&g_desc[j], 0ull);
                unsigned st = (unsigned)(d >> 32);
                if (st == 0) continue;            // not yet published
                sum += (unsigned)d;
                if (st == 2) break;               // inclusive prefix
                j--;                              // aggregate: keep walking
            }
            atomicExch(&g_desc[b], (2ull << 32) | (sum + agg));
            sprefix = (int)sum;
            if (b == NBLK - 1) g_rowptr[NN] = (int)(sum + agg);
        }
    }
    __syncthreads();
    if (i < NN) g_rowptr[i] = s - v + warps[w] + sprefix;
}

// atomic-free CSR fill: pos = rowptr[dst] + per-edge slot from deg_acc
__global__ void k_fill(const int* __restrict__ ei,
                       const float* __restrict__ ew) {
    int e = blockIdx.x * blockDim.x + threadIdx.x;
    if (e >= NE) return;
    int s = ei[e], d = ei[NE + e];
    int pos = g_rowptr[d] + g_eli[e];
    float w = g_dinv[s] * ew[e] * g_dinv[d];
    g_csr[pos] = make_int2(s, __float_as_int(w));
}

// ------------- tensor-core GEMM: fp16 A x (fp16 hi+lo) W -------------------
__global__ __launch_bounds__(256) void k_gemm_tc(const void* __restrict__ Ap,
                                                 int widx, int fp32_in) {
    extern __shared__ __half sm[];
    __half* Ah = sm;                    // 128 x GP
    __half* Wh = sm + 128 * GP;
    __half* Wl = Wh + 128 * GP;
    int tid = threadIdx.x;
    int wid = tid >> 5;
    int row0 = blockIdx.x * 128;
    const __half* __restrict__ Whig = g_Whi[widx];
    const __half* __restrict__ Wlog = g_Wlo[widx];

    if (fp32_in) {
        const float* __restrict__ A = (const float*)Ap;
        #pragma unroll
        for (int i = 0; i < 8; i++) {
            int idx = tid + i * 256;
            int r = idx >> 4, q = idx & 15;
            int row = row0 + r;
            uint4 o = make_uint4(0u, 0u, 0u, 0u);
            if (row < NN) {
                float4 a = *(const float4*)&A[(size_t)row * F + q * 8];
                float4 b = *(const float4*)&A[(size_t)row * F + q * 8 + 4];
                __half2 h0 = __float22half2_rn(make_float2(a.x, a.y));
                __half2 h1 = __float22half2_rn(make_float2(a.z, a.w));
                __half2 h2 = __float22half2_rn(make_float2(b.x, b.y));
                __half2 h3 = __float22half2_rn(make_float2(b.z, b.w));
                o.x = *(uint32_t*)&h0; o.y = *(uint32_t*)&h1;
                o.z = *(uint32_t*)&h2; o.w = *(uint32_t*)&h3;
            }
            *(uint4*)&Ah[r * GP + q * 8] = o;
        }
    } else {
        const __half* __restrict__ A = (const __half*)Ap;
        #pragma unroll
        for (int i = 0; i < 8; i++) {
            int idx = tid + i * 256;
            int r = idx >> 4, q = idx & 15;
            int row = row0 + r;
            uint4 v = make_uint4(0u, 0u, 0u, 0u);
            if (row < NN) v = *(const uint4*)&A[(size_t)row * F + q * 8];
            *(uint4*)&Ah[r * GP + q * 8] = v;
        }
    }
    #pragma unroll
    for (int i = 0; i < 8; i++) {
        int idx = tid + i * 256;
        int k = idx >> 4, q = idx & 15;
        *(uint4*)&Wh[k * GP + q * 8] = *(const uint4*)&Whig[k * F + q * 8];
        *(uint4*)&Wl[k * GP + q * 8] = *(const uint4*)&Wlog[k * F + q * 8];
    }
    __syncthreads();

    wmma::fragment<wmma::accumulator, 16, 16, 16, float> acc[8];
    #pragma unroll
    for (int c = 0; c < 8; c++) wmma::fill_fragment(acc[c], 0.0f);

    #pragma unroll
    for (int ks = 0; ks < 8; ks++) {
        wmma::fragment<wmma::matrix_a, 16, 16, 16, __half, wmma::row_major> a;
        wmma::load_matrix_sync(a, &Ah[(wid * 16) * GP + ks * 16], GP);
        #pragma unroll
        for (int c = 0; c < 8; c++) {
            wmma::fragment<wmma::matrix_b, 16, 16, 16, __half,
                           wmma::row_major> bh, bl;
            wmma::load_matrix_sync(bh, &Wh[(ks * 16) * GP + c * 16], GP);
            wmma::load_matrix_sync(bl, &Wl[(ks * 16) * GP + c * 16], GP);
            wmma::mma_sync(acc[c], a, bh, acc[c]);
            wmma::mma_sync(acc[c], a, bl, acc[c]);
        }
    }
    __half* outp = &g_h[(size_t)(row0 + wid * 16) * F];
    #pragma unroll
    for (int c = 0; c < 8; c++) {
        wmma::fragment<wmma::accumulator, 16, 16, 16, __half> hacc;
        #pragma unroll
        for (int i = 0; i < 8; i++) hacc.x[i] = __float2half(acc[c].x[i]);
        wmma::store_matrix_sync(outp + c * 16, hacc, F, wmma::mem_row_major);
    }
}

// ----------------------- aggregation: CSR gather ----------------------------
// 2 nodes per warp: 16 lanes per node, uint4 (8 fp16) per lane per edge-row.
// NOTE: macro params underscore-prefixed — a bare `w` param would be
// substituted into the `.w` member access by the preprocessor.
#define ROW_FMA8(_wt, _v)                                                    \
    do {                                                                     \
        float2 _a0 = __half22float2(*(__half2*)&(_v).x);                     \
        float2 _a1 = __half22float2(*(__half2*)&(_v).y);                     \
        float2 _a2 = __half22float2(*(__half2*)&(_v).z);                     \
        float2 _a3 = __half22float2(*(__half2*)&(_v).w);                     \
        acc0.x += (_wt) * _a0.x; acc0.y += (_wt) * _a0.y;                    \
        acc0.z += (_wt) * _a1.x; acc0.w += (_wt) * _a1.y;                    \
        acc1.x += (_wt) * _a2.x; acc1.y += (_wt) * _a2.y;                    \
        acc1.z += (_wt) * _a3.x; acc1.w += (_wt) * _a3.y;                    \
    } while (0)

__global__ __launch_bounds__(256) void k_gather(const float* __restrict__ b,
                                                int do_dot,
                                                const float* __restrict__ Wf) {
    int lane = threadIdx.x & 31;
    int sl = lane & 15;
    int node = blockIdx.x * 16 + ((threadIdx.x >> 5) << 1) + (lane >> 4);
    // NN == 6250*16 exactly; no guard needed
    const uint4* __restrict__ h4 = (const uint4*)g_h;

    float dv = g_dinv[node];
    float s2 = dv * dv;
    uint4 hv = h4[(size_t)node * 16 + sl];
    float4 acc0, acc1;
    {
        float2 a0 = __half22float2(*(__half2*)&hv.x);
        float2 a1 = __half22float2(*(__half2*)&hv.y);
        float2 a2 = __half22float2(*(__half2*)&hv.z);
        float2 a3 = __half22float2(*(__half2*)&hv.w);
        float4 b0 = *(const float4*)&b[sl * 8];
        float4 b1 = *(const float4*)&b[sl * 8 + 4];
        acc0.x = s2 * a0.x + b0.x; acc0.y = s2 * a0.y + b0.y;
        acc0.z = s2 * a1.x + b0.z; acc0.w = s2 * a1.y + b0.w;
        acc1.x = s2 * a2.x + b1.x; acc1.y = s2 * a2.y + b1.y;
        acc1.z = s2 * a3.x + b1.z; acc1.w = s2 * a3.y + b1.w;
    }

    int beg = g_rowptr[node], end = g_rowptr[node + 1];
    int e = beg;
    for (; e + 2 <= end; e += 2) {               // 2 edges in flight
        int2 p0 = g_csr[e];
        int2 p1 = g_csr[e + 1];
        float w0 = __int_as_float(p0.y);
        float w1 = __int_as_float(p1.y);
        uint4 v0 = h4[(size_t)p0.x * 16 + sl];
        uint4 v1 = h4[(size_t)p1.x * 16 + sl];
        ROW_FMA8(w0, v0);
        ROW_FMA8(w1, v1);
    }
    if (e < end) {
        int2 p = g_csr[e];
        float wz = __int_as_float(p.y);
        uint4 v = h4[(size_t)p.x * 16 + sl];
        ROW_FMA8(wz, v);
    }

    acc0.x = fmaxf(acc0.x, 0.f); acc0.y = fmaxf(acc0.y, 0.f);
    acc0.z = fmaxf(acc0.z, 0.f); acc0.w = fmaxf(acc0.w, 0.f);
    acc1.x = fmaxf(acc1.x, 0.f); acc1.y = fmaxf(acc1.y, 0.f);
    acc1.z = fmaxf(acc1.z, 0.f); acc1.w = fmaxf(acc1.w, 0.f);

    if (!do_dot) {
        __half2 o0 = __float22half2_rn(make_float2(acc0.x, acc0.y));
        __half2 o1 = __float22half2_rn(make_float2(acc0.z, acc0.w));
        __half2 o2 = __float22half2_rn(make_float2(acc1.x, acc1.y));
        __half2 o3 = __float22half2_rn(make_float2(acc1.z, acc1.w));
        uint4 o;
        o.x = *(uint32_t*)&o0; o.y = *(uint32_t*)&o1;
        o.z = *(uint32_t*)&o2; o.w = *(uint32_t*)&o3;
        ((uint4*)g_buf)[(size_t)node * 16 + sl] = o;
    } else {
        float4 wf0 = *(const float4*)&Wf[sl * 8];
        float4 wf1 = *(const float4*)&Wf[sl * 8 + 4];
        float sum = acc0.x * wf0.x + acc0.y * wf0.y +
                    acc0.z * wf0.z + acc0.w * wf0.w +
                    acc1.x * wf1.x + acc1.y * wf1.y +
                    acc1.z * wf1.z + acc1.w * wf1.w;
        #pragma unroll
        for (int o = 1; o < 16; o <<= 1)          // reduce within 16-lane half
            sum += __shfl_xor_sync(0xffffffffu, sum, o);
        if (sl == 0) g_hf[node] = sum;
    }
}

// ------------------------------ final layer --------------------------------
__global__ void k_fin(const float* __restrict__ bf, float* __restrict__ out) {
    int i = blockIdx.x * blockDim.x + threadIdx.x;
    if (i >= NN) return;
    float dv = g_dinv[i];
    float acc = dv * dv * g_hf[i] + bf[0];
    int beg = g_rowptr[i], end = g_rowptr[i + 1];
    for (int e = beg; e < end; e++) {
        int2 p = g_csr[e];
        acc += __int_as_float(p.y) * g_hf[p.x];
    }
    out[i] = acc;
}

// ------------------------------- launch ------------------------------------
extern "C" void kernel_launch(void* const* d_in, const int* in_sizes, int n_in,
                              void* d_out, int out_size) {
    const float* x   = (const float*)d_in[0];
    const int*   ei  = (const int*)d_in[1];
    const float* ew  = (const float*)d_in[2];
    const float* Win = (const float*)d_in[3];
    const float* bin = (const float*)d_in[4];
    const float* Wmd = (const float*)d_in[5];
    const float* bmd = (const float*)d_in[6];
    const float* Wfn = (const float*)d_in[7];
    const float* bfn = (const float*)d_in[8];
    float* out = (float*)d_out;

    static cudaStream_t sA = nullptr;
    static cudaEvent_t evFork = nullptr, evJoin = nullptr;
    if (!sA) {
        cudaFuncSetAttribute(k_gemm_tc,
                             cudaFuncAttributeMaxDynamicSharedMemorySize,
                             SMEM_G);
        cudaStreamCreateWithFlags(&sA, cudaStreamNonBlocking);
        cudaEventCreateWithFlags(&evFork, cudaEventDisableTiming);
        cudaEventCreateWithFlags(&evJoin, cudaEventDisableTiming);
    }

    __half* buf16;
    cudaGetSymbolAddress((void**)&buf16, g_buf);

    const int TB = 256;
    const int gN = (NN + TB - 1) / TB;           // 391
    const int gE = (NE + TB - 1) / TB;           // 6250
    const int gG = (NNP + 127) / 128;            // 782
    const int gA = NN / 16;                      // 6250 (2 nodes/warp)

    // prelude on main stream (init + W split)
    k_pre<<<gN + 128, TB>>>(Win, Wmd);           // 0
    cudaEventRecord(evFork, 0);

    // CSR-build chain on side stream, overlapped with GEMM-1 on main stream
    cudaStreamWaitEvent(sA, evFork, 0);
    k_deg_acc<<<gE, TB, 0, sA>>>(ei, ew);        // 1
    k_scan<<<NBLK, 1024, 0, sA>>>();             // 2
    k_fill<<<gE, TB, 0, sA>>>(ei, ew);           // 3
    cudaEventRecord(evJoin, sA);

    k_gemm_tc<<<gG, TB, SMEM_G>>>(x, 0, 1);      // 4 (fp32 x in)
    cudaStreamWaitEvent(0, evJoin, 0);

    // layer 1 aggregate
    k_gather<<<gA, TB>>>(bin, 0, nullptr);       // 5  <-- profiled

    // layer 2
    k_gemm_tc<<<gG, TB, SMEM_G>>>(buf16, 1, 0);  // 6
    k_gather<<<gA, TB>>>(bmd, 0, nullptr);       // 7

    // layer 3 (+ fused final dot)
    k_gemm_tc<<<gG, TB, SMEM_G>>>(buf16, 1, 0);  // 8
    k_gather<<<gA, TB>>>(bmd, 1, Wfn);           // 9

    // final aggregation (scalar)
    k_fin<<<gN, TB>>>(bfn, out);                 // 10
}

// round 17
// speedup vs baseline: 2.5088x; 1.0144x over previous
#include <cuda_runtime.h>
#include <cuda_fp16.h>
#include <cstdint>
#include <mma.h>

using namespace nvcuda;

#define NN 100000
#define NNP 100096   // padded to multiple of 128 for unguarded wmma stores
#define NE 1600000
#define F 128
#define NBLK 98      // ceil(NN/1024)
#define GP 136       // GEMM smem pitch (fp16)
#define SMEM_G (3 * 128 * GP * 2)   // 104448 B: A + Whi + Wlo
#define WSCALE 16777216.0f          // 2^24 fixed-point for edge weights
#define SPLIT 50048                 // = 391*128, half boundary (rows & nodes)

// -------- scratch (static device globals; no allocations allowed) ----------
__device__ float g_dinv[NN];
__device__ unsigned long long g_cnt[NN];      // count<<40 | wsum*2^24
__device__ unsigned long long g_desc[NBLK];   // lookback: status<<32 | value
__device__ int   g_rowptr[NN + 1];
__device__ int   g_eli[NE];                   // edge's index within dst row
__device__ __align__(16) int2 g_csr[NE];
__device__ __align__(16) __half g_hA[(size_t)NNP * F];    // h ping
__device__ __align__(16) __half g_hB[(size_t)NNP * F];    // h pong
__device__ __align__(16) __half g_buf[(size_t)NNP * F];   // relu(agg) (fp16)
__device__ float g_hf[NN];
__device__ __align__(16) __half g_Whi[2][F * F];  // [0]=W_in, [1]=W_mid
__device__ __align__(16) __half g_Wlo[2][F * F];

// ------------------- init + W split (merged prelude) ------------------------
__global__ void k_pre(const float* __restrict__ Win,
                      const float* __restrict__ Wmd) {
    int bid = blockIdx.x;
    if (bid < 391) {
        int i = bid * 256 + threadIdx.x;
        if (i < NN) g_cnt[i] = 0ull;
        if (i < NBLK) g_desc[i] = 0ull;
    } else {
        int r = bid - 391;                        // 0..127
        int which = r >> 6;                       // 0=W_in, 1=W_mid
        int i = (r & 63) * 256 + threadIdx.x;     // 0..16383
        const float* W = which ? Wmd : Win;
        float w = W[i];
        __half h = __float2half(w);
        g_Whi[which][i] = h;
        g_Wlo[which][i] = __float2half(w - __half2float(h));
    }
}

// one packed 64-bit atomic: bits[40,64)=count, bits[0,40)=wsum fixed-point
__global__ void k_deg_acc(const int* __restrict__ ei,
                          const float* __restrict__ ew) {
    int e = blockIdx.x * blockDim.x + threadIdx.x;
    if (e < NE) {
        int d = ei[NE + e];
        unsigned long long inc =
            (1ull << 40) | (unsigned long long)__float2uint_rn(ew[e] * WSCALE);
        unsigned long long old = atomicAdd(&g_cnt[d], inc);
        g_eli[e] = (int)(old >> 40);
    }
}

// ------------- single-pass exclusive scan (decoupled lookback) --------------
__global__ __launch_bounds__(1024) void k_scan() {
    __shared__ int warps[32];
    __shared__ int sprefix;
    int t = threadIdx.x, b = blockIdx.x, i = b * 1024 + t;
    int v = 0;
    if (i < NN) {
        unsigned long long pk = g_cnt[i];
        v = (int)(pk >> 40);
        float wsum = (float)(pk & ((1ull << 40) - 1)) * (1.0f / WSCALE);
        g_dinv[i] = rsqrtf(1.0f + wsum);          // deg >= 1 always
    }
    int lane = t & 31, w = t >> 5;

    int s = v;
    #pragma unroll
    for (int o = 1; o < 32; o <<= 1) {
        int u = __shfl_up_sync(0xffffffffu, s, o);
        if (lane >= o) s += u;
    }
    if (lane == 31) warps[w] = s;
    __syncthreads();

    if (w == 0) {
        int ws = warps[lane];
        int ss = ws;
        #pragma unroll
        for (int o = 1; o < 32; o <<= 1) {
            int u = __shfl_up_sync(0xffffffffu, ss, o);
            if (lane >= o) ss += u;
        }
        warps[lane] = ss - ws;                    // exclusive warp offsets
        if (lane == 31) {
            unsigned agg = (unsigned)ss;          // block total
            atomicExch(&g_desc[b], (1ull << 32) | agg);
            unsigned sum = 0;
            for (int j = b - 1; j >= 0;) {
                unsigned long long d = atomicAdd(&g_desc[j], 0ull);
                unsigned st = (unsigned)(d >> 32);
                if (st == 0) continue;            // not yet published
                sum += (unsigned)d;
                if (st == 2) break;               // inclusive prefix
                j--;                              // aggregate: keep walking
            }
            atomicExch(&g_desc[b], (2ull << 32) | (sum + agg));
            sprefix = (int)sum;
            if (b == NBLK - 1) g_rowptr[NN] = (int)(sum + agg);
        }
    }
    __syncthreads();
    if (i < NN) g_rowptr[i] = s - v + warps[w] + sprefix;
}

// atomic-free CSR fill: pos = rowptr[dst] + per-edge slot from deg_acc
__global__ void k_fill(const int* __restrict__ ei,
                       const float* __restrict__ ew) {
    int e = blockIdx.x * blockDim.x + threadIdx.x;
    if (e >= NE) return;
    int s = ei[e], d = ei[NE + e];
    int pos = g_rowptr[d] + g_eli[e];
    float w = g_dinv[s] * ew[e] * g_dinv[d];
    g_csr[pos] = make_int2(s, __float_as_int(w));
}

// ------------- tensor-core GEMM: fp16 A x (fp16 hi+lo) W -------------------
// row range = [row_base, row_base + gridDim.x*128)
__global__ __launch_bounds__(256) void k_gemm_tc(const void* __restrict__ Ap,
                                                 __half* __restrict__ Hout,
                                                 int widx, int fp32_in,
                                                 int row_base) {
    extern __shared__ __half sm[];
    __half* Ah = sm;                    // 128 x GP
    __half* Wh = sm + 128 * GP;
    __half* Wl = Wh + 128 * GP;
    int tid = threadIdx.x;
    int wid = tid >> 5;
    int row0 = row_base + blockIdx.x * 128;
    const __half* __restrict__ Whig = g_Whi[widx];
    const __half* __restrict__ Wlog = g_Wlo[widx];

    if (fp32_in) {
        const float* __restrict__ A = (const float*)Ap;
        #pragma unroll
        for (int i = 0; i < 8; i++) {
            int idx = tid + i * 256;
            int r = idx >> 4, q = idx & 15;
            int row = row0 + r;
            uint4 o = make_uint4(0u, 0u, 0u, 0u);
            if (row < NN) {
                float4 a = *(const float4*)&A[(size_t)row * F + q * 8];
                float4 b = *(const float4*)&A[(size_t)row * F + q * 8 + 4];
                __half2 h0 = __float22half2_rn(make_float2(a.x, a.y));
                __half2 h1 = __float22half2_rn(make_float2(a.z, a.w));
                __half2 h2 = __float22half2_rn(make_float2(b.x, b.y));
                __half2 h3 = __float22half2_rn(make_float2(b.z, b.w));
                o.x = *(uint32_t*)&h0; o.y = *(uint32_t*)&h1;
                o.z = *(uint32_t*)&h2; o.w = *(uint32_t*)&h3;
            }
            *(uint4*)&Ah[r * GP + q * 8] = o;
        }
    } else {
        const __half* __restrict__ A = (const __half*)Ap;
        #pragma unroll
        for (int i = 0; i < 8; i++) {
            int idx = tid + i * 256;
            int r = idx >> 4, q = idx & 15;
            int row = row0 + r;
            uint4 v = make_uint4(0u, 0u, 0u, 0u);
            if (row < NN) v = *(const uint4*)&A[(size_t)row * F + q * 8];
            *(uint4*)&Ah[r * GP + q * 8] = v;
        }
    }
    #pragma unroll
    for (int i = 0; i < 8; i++) {
        int idx = tid + i * 256;
        int k = idx >> 4, q = idx & 15;
        *(uint4*)&Wh[k * GP + q * 8] = *(const uint4*)&Whig[k * F + q * 8];
        *(uint4*)&Wl[k * GP + q * 8] = *(const uint4*)&Wlog[k * F + q * 8];
    }
    __syncthreads();

    wmma::fragment<wmma::accumulator, 16, 16, 16, float> acc[8];
    #pragma unroll
    for (int c = 0; c < 8; c++) wmma::fill_fragment(acc[c], 0.0f);

    #pragma unroll
    for (int ks = 0; ks < 8; ks++) {
        wmma::fragment<wmma::matrix_a, 16, 16, 16, __half, wmma::row_major> a;
        wmma::load_matrix_sync(a, &Ah[(wid * 16) * GP + ks * 16], GP);
        #pragma unroll
        for (int c = 0; c < 8; c++) {
            wmma::fragment<wmma::matrix_b, 16, 16, 16, __half,
                           wmma::row_major> bh, bl;
            wmma::load_matrix_sync(bh, &Wh[(ks * 16) * GP + c * 16], GP);
            wmma::load_matrix_sync(bl, &Wl[(ks * 16) * GP + c * 16], GP);
            wmma::mma_sync(acc[c], a, bh, acc[c]);
            wmma::mma_sync(acc[c], a, bl, acc[c]);
        }
    }
    __half* outp = &Hout[(size_t)(row0 + wid * 16) * F];
    #pragma unroll
    for (int c = 0; c < 8; c++) {
        wmma::fragment<wmma::accumulator, 16, 16, 16, __half> hacc;
        #pragma unroll
        for (int i = 0; i < 8; i++) hacc.x[i] = __float2half(acc[c].x[i]);
        wmma::store_matrix_sync(outp + c * 16, hacc, F, wmma::mem_row_major);
    }
}

// ----------------------- aggregation: CSR gather ----------------------------
// 2 nodes per warp: 16 lanes per node, uint4 (8 fp16) per lane per edge-row.
// (macro params underscore-prefixed: bare `w` would hit `.w` member tokens)
#define ROW_FMA8(_wt, _v)                                                    \
    do {                                                                     \
        float2 _a0 = __half22float2(*(__half2*)&(_v).x);                     \
        float2 _a1 = __half22float2(*(__half2*)&(_v).y);                     \
        float2 _a2 = __half22float2(*(__half2*)&(_v).z);                     \
        float2 _a3 = __half22float2(*(__half2*)&(_v).w);                     \
        acc0.x += (_wt) * _a0.x; acc0.y += (_wt) * _a0.y;                    \
        acc0.z += (_wt) * _a1.x; acc0.w += (_wt) * _a1.y;                    \
        acc1.x += (_wt) * _a2.x; acc1.y += (_wt) * _a2.y;                    \
        acc1.z += (_wt) * _a3.x; acc1.w += (_wt) * _a3.y;                    \
    } while (0)

__global__ __launch_bounds__(256) void k_gather(const __half* __restrict__ H,
                                                const float* __restrict__ b,
                                                int do_dot,
                                                const float* __restrict__ Wf,
                                                int node_base) {
    int lane = threadIdx.x & 31;
    int sl = lane & 15;
    int node = node_base + blockIdx.x * 16 + ((threadIdx.x >> 5) << 1)
             + (lane >> 4);
    // ranges are exact multiples of 16; no guard needed
    const uint4* __restrict__ h4 = (const uint4*)H;

    float dv = g_dinv[node];
    float s2 = dv * dv;
    uint4 hv = h4[(size_t)node * 16 + sl];
    float4 acc0, acc1;
    {
        float2 a0 = __half22float2(*(__half2*)&hv.x);
        float2 a1 = __half22float2(*(__half2*)&hv.y);
        float2 a2 = __half22float2(*(__half2*)&hv.z);
        float2 a3 = __half22float2(*(__half2*)&hv.w);
        float4 b0 = *(const float4*)&b[sl * 8];
        float4 b1 = *(const float4*)&b[sl * 8 + 4];
        acc0.x = s2 * a0.x + b0.x; acc0.y = s2 * a0.y + b0.y;
        acc0.z = s2 * a1.x + b0.z; acc0.w = s2 * a1.y + b0.w;
        acc1.x = s2 * a2.x + b1.x; acc1.y = s2 * a2.y + b1.y;
        acc1.z = s2 * a3.x + b1.z; acc1.w = s2 * a3.y + b1.w;
    }

    int beg = g_rowptr[node], end = g_rowptr[node + 1];
    int e = beg;
    for (; e + 2 <= end; e += 2) {               // 2 edges in flight
        int2 p0 = g_csr[e];
        int2 p1 = g_csr[e + 1];
        float w0 = __int_as_float(p0.y);
        float w1 = __int_as_float(p1.y);
        uint4 v0 = h4[(size_t)p0.x * 16 + sl];
        uint4 v1 = h4[(size_t)p1.x * 16 + sl];
        ROW_FMA8(w0, v0);
        ROW_FMA8(w1, v1);
    }
    if (e < end) {
        int2 p = g_csr[e];
        float wz = __int_as_float(p.y);
        uint4 v = h4[(size_t)p.x * 16 + sl];
        ROW_FMA8(wz, v);
    }

    acc0.x = fmaxf(acc0.x, 0.f); acc0.y = fmaxf(acc0.y, 0.f);
    acc0.z = fmaxf(acc0.z, 0.f); acc0.w = fmaxf(acc0.w, 0.f);
    acc1.x = fmaxf(acc1.x, 0.f); acc1.y = fmaxf(acc1.y, 0.f);
    acc1.z = fmaxf(acc1.z, 0.f); acc1.w = fmaxf(acc1.w, 0.f);

    if (!do_dot) {
        __half2 o0 = __float22half2_rn(make_float2(acc0.x, acc0.y));
        __half2 o1 = __float22half2_rn(make_float2(acc0.z, acc0.w));
        __half2 o2 = __float22half2_rn(make_float2(acc1.x, acc1.y));
        __half2 o3 = __float22half2_rn(make_float2(acc1.z, acc1.w));
        uint4 o;
        o.x = *(uint32_t*)&o0; o.y = *(uint32_t*)&o1;
        o.z = *(uint32_t*)&o2; o.w = *(uint32_t*)&o3;
        ((uint4*)g_buf)[(size_t)node * 16 + sl] = o;
    } else {
        float4 wf0 = *(const float4*)&Wf[sl * 8];
        float4 wf1 = *(const float4*)&Wf[sl * 8 + 4];
        float sum = acc0.x * wf0.x + acc0.y * wf0.y +
                    acc0.z * wf0.z + acc0.w * wf0.w +
                    acc1.x * wf1.x + acc1.y * wf1.y +
                    acc1.z * wf1.z + acc1.w * wf1.w;
        #pragma unroll
        for (int o = 1; o < 16; o <<= 1)          // reduce within 16-lane half
            sum += __shfl_xor_sync(0xffffffffu, sum, o);
        if (sl == 0) g_hf[node] = sum;
    }
}

// ------------------------------ final layer --------------------------------
__global__ void k_fin(const float* __restrict__ bf, float* __restrict__ out) {
    int i = blockIdx.x * blockDim.x + threadIdx.x;
    if (i >= NN) return;
    float dv = g_dinv[i];
    float acc = dv * dv * g_hf[i] + bf[0];
    int beg = g_rowptr[i], end = g_rowptr[i + 1];
    for (int e = beg; e < end; e++) {
        int2 p = g_csr[e];
        acc += __int_as_float(p.y) * g_hf[p.x];
    }
    out[i] = acc;
}

// ------------------------------- launch ------------------------------------
extern "C" void kernel_launch(void* const* d_in, const int* in_sizes, int n_in,
                              void* d_out, int out_size) {
    const float* x   = (const float*)d_in[0];
    const int*   ei  = (const int*)d_in[1];
    const float* ew  = (const float*)d_in[2];
    const float* Win = (const float*)d_in[3];
    const float* bin = (const float*)d_in[4];
    const float* Wmd = (const float*)d_in[5];
    const float* bmd = (const float*)d_in[6];
    const float* Wfn = (const float*)d_in[7];
    const float* bfn = (const float*)d_in[8];
    float* out = (float*)d_out;

    static cudaStream_t sS = nullptr;
    static cudaEvent_t ev[8];
    if (!sS) {
        cudaFuncSetAttribute(k_gemm_tc,
                             cudaFuncAttributeMaxDynamicSharedMemorySize,
                             SMEM_G);
        cudaStreamCreateWithFlags(&sS, cudaStreamNonBlocking);
        for (int i = 0; i < 8; i++)
            cudaEventCreateWithFlags(&ev[i], cudaEventDisableTiming);
    }

    __half *hA, *hB, *buf16;
    cudaGetSymbolAddress((void**)&hA, g_hA);
    cudaGetSymbolAddress((void**)&hB, g_hB);
    cudaGetSymbolAddress((void**)&buf16, g_buf);

    const int TB = 256;
    const int gN = (NN + TB - 1) / TB;           // 391
    const int gE = (NE + TB - 1) / TB;           // 6250
    const int gGa = SPLIT / 128;                 // 391 (rows [0, 50048))
    const int gGb = (NNP - SPLIT) / 128;         // 391 (rows [50048, 100096))
    const int gAa = SPLIT / 16;                  // 3128 (nodes [0, 50048))
    const int gAb = (NN - SPLIT) / 16;           // 3122 (nodes [50048, 100000))

    // ---- prelude: main = init+Wsplit, side = CSR chain, main = GEMM-1 ----
    k_pre<<<gN + 128, TB>>>(Win, Wmd);
    cudaEventRecord(ev[0], 0);
    cudaStreamWaitEvent(sS, ev[0], 0);
    k_deg_acc<<<gE, TB, 0, sS>>>(ei, ew);
    k_scan<<<NBLK, 1024, 0, sS>>>();
    k_fill<<<gE, TB, 0, sS>>>(ei, ew);
    cudaEventRecord(ev[1], sS);                  // CSR ready

    k_gemm_tc<<<782, TB, SMEM_G>>>(x, hA, 0, 1, 0);   // GEMM-1 whole, -> hA
    cudaEventRecord(ev[2], 0);                   // hA ready
    cudaStreamWaitEvent(0, ev[1], 0);

    // ---- layer 1 gather halves; layer 2 GEMM halves pipelined ----
    k_gather<<<gAa, TB>>>(hA, bin, 0, nullptr, 0);            // M: g1a
    cudaStreamWaitEvent(sS, ev[2], 0);
    k_gather<<<gAb, TB, 0, sS>>>(hA, bin, 0, nullptr, SPLIT); // S: g1b
    k_gemm_tc<<<gGa, TB, SMEM_G>>>(buf16, hB, 1, 0, 0);       // M: gemm2a
    k_gemm_tc<<<gGb, TB, SMEM_G, sS>>>(buf16, hB, 1, 0, SPLIT); // S: gemm2b
    cudaEventRecord(ev[3], 0);                   // gemm2a done
    cudaEventRecord(ev[4], sS);                  // gemm2b done
    cudaStreamWaitEvent(0, ev[4], 0);
    cudaStreamWaitEvent(sS, ev[3], 0);

    // ---- layer 2 gather halves; layer 3 GEMM halves pipelined ----
    k_gather<<<gAa, TB>>>(hB, bmd, 0, nullptr, 0);            // M: g2a
    k_gather<<<gAb, TB, 0, sS>>>(hB, bmd, 0, nullptr, SPLIT); // S: g2b
    k_gemm_tc<<<gGa, TB, SMEM_G>>>(buf16, hA, 1, 0, 0);       // M: gemm3a
    k_gemm_tc<<<gGb, TB, SMEM_G, sS>>>(buf16, hA, 1, 0, SPLIT); // S: gemm3b
    cudaEventRecord(ev[5], 0);
    cudaEventRecord(ev[6], sS);
    cudaStreamWaitEvent(0, ev[6], 0);
    cudaStreamWaitEvent(sS, ev[5], 0);

    // ---- layer 3 gather (fused final dot) halves ----
    k_gather<<<gAa, TB>>>(hA, bmd, 1, Wfn, 0);                // M: g3a
    k_gather<<<gAb, TB, 0, sS>>>(hA, bmd, 1, Wfn, SPLIT);     // S: g3b
    cudaEventRecord(ev[7], sS);
    cudaStreamWaitEvent(0, ev[7], 0);

    // final aggregation (scalar)
    k_fin<<<gN, TB>>>(bfn, out);
}